// round 6
// baseline (speedup 1.0000x reference)
#include <cuda_runtime.h>

#define S_LEN  4096
#define BATCH  2
#define NH     12
#define HD     64
#define E_DIM  768
#define QKV_N  2304
#define NTOK   (BATCH * S_LEN)
#define NQB    (S_LEN / 128)          // 32 q-blocks per (b,h)

// Scratch (allocation-free rule: __device__ globals). All tf32-pre-rounded.
__device__ float g_Q[(size_t)BATCH * NH * S_LEN * HD];   // pre-scaled by 0.125*log2e
__device__ float g_K[(size_t)BATCH * NH * S_LEN * HD];
__device__ float g_V[(size_t)BATCH * NH * S_LEN * HD];
__device__ float g_Att[(size_t)NTOK * E_DIM];            // attended, rounded
__device__ float g_Xr[(size_t)NTOK * E_DIM];             // rounded x
__device__ float g_Wq[(size_t)E_DIM * QKV_N];            // rounded w_qkv
__device__ float g_Wo[(size_t)E_DIM * E_DIM];            // rounded w_out

// ---------------------------------------------------------------------------
// helpers
// ---------------------------------------------------------------------------
__device__ __forceinline__ unsigned f2tf32(float f) {
    unsigned u;
    asm("cvt.rna.tf32.f32 %0, %1;" : "=r"(u) : "f"(f));
    return u;
}
__device__ __forceinline__ float f2tf32f(float f) {
    return __uint_as_float(f2tf32(f));
}
__device__ __forceinline__ float ex2f(float x) {
    float y;
    asm("ex2.approx.f32 %0, %1;" : "=f"(y) : "f"(x));
    return y;
}

__device__ __forceinline__ void mma_tf32(float c[4],
    unsigned a0, unsigned a1, unsigned a2, unsigned a3,
    unsigned b0, unsigned b1)
{
    asm volatile(
        "mma.sync.aligned.m16n8k8.row.col.f32.tf32.tf32.f32 "
        "{%0,%1,%2,%3}, {%4,%5,%6,%7}, {%8,%9}, {%0,%1,%2,%3};\n"
        : "+f"(c[0]), "+f"(c[1]), "+f"(c[2]), "+f"(c[3])
        : "r"(a0), "r"(a1), "r"(a2), "r"(a3), "r"(b0), "r"(b1));
}

__device__ __forceinline__ void cp16(void* s, const void* g) {
    unsigned sa = (unsigned)__cvta_generic_to_shared(s);
    asm volatile("cp.async.cg.shared.global [%0], [%1], 16;\n" :: "r"(sa), "l"(g));
}
#define CP_COMMIT() asm volatile("cp.async.commit_group;\n")
#define CP_WAIT(N)  asm volatile("cp.async.wait_group %0;\n" :: "n"(N))

// scale folded into Q: 1/sqrt(64) * log2(e)
#define QSCALE 0.1803368801111204f

// ---------------------------------------------------------------------------
// Kernel 0: pre-round inputs to tf32 (enables raw cp.async staging everywhere)
// ---------------------------------------------------------------------------
__global__ void prepass(const float* __restrict__ x,
                        const float* __restrict__ wq,
                        const float* __restrict__ wo)
{
    const int stride = gridDim.x * blockDim.x;
    const int tid = blockIdx.x * blockDim.x + threadIdx.x;
    const int nx = NTOK * E_DIM / 4, nq = E_DIM * QKV_N / 4, no = E_DIM * E_DIM / 4;
    for (int i = tid; i < nx; i += stride) {
        float4 v = ((const float4*)x)[i];
        ((float4*)g_Xr)[i] = make_float4(f2tf32f(v.x), f2tf32f(v.y), f2tf32f(v.z), f2tf32f(v.w));
    }
    for (int i = tid; i < nq; i += stride) {
        float4 v = ((const float4*)wq)[i];
        ((float4*)g_Wq)[i] = make_float4(f2tf32f(v.x), f2tf32f(v.y), f2tf32f(v.z), f2tf32f(v.w));
    }
    for (int i = tid; i < no; i += stride) {
        float4 v = ((const float4*)wo)[i];
        ((float4*)g_Wo)[i] = make_float4(f2tf32f(v.x), f2tf32f(v.y), f2tf32f(v.z), f2tf32f(v.w));
    }
}

// ---------------------------------------------------------------------------
// GEMM common: 128x128 tile, BK=32, 3-stage cp.async, tf32 MMA.
// ---------------------------------------------------------------------------
#define GA_ST 36
#define GB_ST 136
#define GA_SZ (128 * GA_ST)
#define GB_SZ (32 * GB_ST)
#define GEMM_SMEM (3 * (GA_SZ + GB_SZ) * 4)

// ---------------------------------------------------------------------------
// Kernel 1: QKV projection. C[8192,2304] = Xr @ Wq + b, scatter to Q/K/V.
// ---------------------------------------------------------------------------
__global__ __launch_bounds__(256) void qkv_gemm(const float* __restrict__ bias)
{
    extern __shared__ unsigned smg[];
    unsigned* Asb = smg;                 // [3][128][GA_ST]
    unsigned* Bsb = smg + 3 * GA_SZ;     // [3][32][GB_ST]

    const int t    = threadIdx.x;
    const int lane = t & 31, warp = t >> 5;
    const int gid  = lane >> 2, tig = lane & 3;
    const int wm   = warp >> 2, wn = warp & 3;
    const int row0 = blockIdx.y * 128;
    const int col0 = blockIdx.x * 128;

    float acc[4][4][4] = {};

    auto stage = [&](int buf, int kk) {
        unsigned* A = Asb + buf * GA_SZ;
        unsigned* B = Bsb + buf * GB_SZ;
#pragma unroll
        for (int i = 0; i < 4; i++) {
            int c = t + i * 256;
            int rr = c >> 3, c4 = (c & 7) * 4;
            cp16(&A[rr * GA_ST + c4], &g_Xr[(size_t)(row0 + rr) * E_DIM + kk + c4]);
        }
#pragma unroll
        for (int i = 0; i < 4; i++) {
            int c = t + i * 256;
            int rr = c >> 5, c4 = (c & 31) * 4;
            cp16(&B[rr * GB_ST + c4], &g_Wq[(size_t)(kk + rr) * QKV_N + col0 + c4]);
        }
        CP_COMMIT();
    };

    const int NT = E_DIM / 32;   // 24
    stage(0, 0);
    stage(1, 32);
    int buf = 0;
    for (int it = 0; it < NT; it++) {
        if (it + 2 < NT)      { stage((it + 2) % 3, (it + 2) * 32); CP_WAIT(2); }
        else if (it + 1 < NT) { CP_WAIT(1); }
        else                  { CP_WAIT(0); }
        __syncthreads();
        unsigned* A = Asb + buf * GA_SZ;
        unsigned* B = Bsb + buf * GB_SZ;
#pragma unroll
        for (int kf = 0; kf < 4; kf++) {
            unsigned a[4][4], b[4][2];
#pragma unroll
            for (int mf = 0; mf < 4; mf++) {
                int m = wm * 64 + mf * 16 + gid;
                a[mf][0] = A[m * GA_ST + kf * 8 + tig];
                a[mf][1] = A[(m + 8) * GA_ST + kf * 8 + tig];
                a[mf][2] = A[m * GA_ST + kf * 8 + tig + 4];
                a[mf][3] = A[(m + 8) * GA_ST + kf * 8 + tig + 4];
            }
#pragma unroll
            for (int nf = 0; nf < 4; nf++) {
                int n = wn * 32 + nf * 8 + gid;
                b[nf][0] = B[(kf * 8 + tig) * GB_ST + n];
                b[nf][1] = B[(kf * 8 + tig + 4) * GB_ST + n];
            }
#pragma unroll
            for (int mf = 0; mf < 4; mf++)
#pragma unroll
                for (int nf = 0; nf < 4; nf++)
                    mma_tf32(acc[mf][nf], a[mf][0], a[mf][1], a[mf][2], a[mf][3],
                             b[nf][0], b[nf][1]);
        }
        __syncthreads();
        buf = (buf + 1) % 3;
    }

    // Epilogue: bias + tf32 round + scatter to Q/K/V [B,H,S,D]
    const int part = col0 / E_DIM;
    float* dst = (part == 0) ? g_Q : (part == 1 ? g_K : g_V);
    const float qs = (part == 0) ? QSCALE : 1.0f;

#pragma unroll
    for (int nf = 0; nf < 4; nf++) {
        int cg = col0 + wn * 32 + nf * 8 + 2 * tig;
        float b0v = bias[cg], b1v = bias[cg + 1];
        int c = cg % E_DIM;
        int h = c >> 6, d = c & 63;
#pragma unroll
        for (int mf = 0; mf < 4; mf++) {
#pragma unroll
            for (int rr = 0; rr < 2; rr++) {
                int m = row0 + wm * 64 + mf * 16 + gid + rr * 8;
                int bb = m >> 12, s = m & 4095;
                size_t o = ((size_t)(bb * NH + h) * S_LEN + s) * HD + d;
                float2 vv;
                vv.x = f2tf32f((acc[mf][nf][rr * 2]     + b0v) * qs);
                vv.y = f2tf32f((acc[mf][nf][rr * 2 + 1] + b1v) * qs);
                *(float2*)&dst[o] = vv;
            }
        }
    }
}

// ---------------------------------------------------------------------------
// Kernel 2: causal flash attention, tf32 MMA + log2-domain softmax.
// Double-buffered cp.async K/V, descending schedule, register-only P
// (quad-shuffle S->A fragment transpose), per-warp masked group skip.
// ---------------------------------------------------------------------------
#define AST 68
#define KST 68
#define VST 72
#define KBUF (64 * KST)
#define VBUF (64 * VST)
#define ATTN_SMEM ((2 * KBUF + 2 * VBUF + 128 * AST) * 4)

__global__ __launch_bounds__(256) void attn_kernel()
{
    extern __shared__ unsigned sm[];
    unsigned* Ksb = sm;                       // [2][64][KST]
    unsigned* Vsb = sm + 2 * KBUF;            // [2][64][VST]
    unsigned* Qs  = sm + 2 * KBUF + 2 * VBUF; // [128][AST] (Q staging only)

    const int t    = threadIdx.x;
    const int lane = t & 31, warp = t >> 5;
    const int gid  = lane >> 2, tig = lane & 3;

    // descending-size schedule: biggest q-blocks first
    const int r  = blockIdx.x;
    const int qb = (NQB - 1) - r / (NH * BATCH);
    const int hb = r % (NH * BATCH);
    const int h  = hb % NH;
    const int b  = hb / NH;
    const int q0 = qb * 128;

    const size_t base = (size_t)(b * NH + h) * S_LEN * HD;
    const float* Qp = g_Q + base;
    const float* Kp = g_K + base;
    const float* Vp = g_V + base;

    auto stage_kv = [&](int buf, int j0) {
        unsigned* K = Ksb + buf * KBUF;
        unsigned* V = Vsb + buf * VBUF;
#pragma unroll
        for (int i = 0; i < 4; i++) {
            int c = t + i * 256;
            int row = c >> 4, c4 = (c & 15) * 4;
            cp16(&K[row * KST + c4], &Kp[(size_t)(j0 + row) * HD + c4]);
            cp16(&V[row * VST + c4], &Vp[(size_t)(j0 + row) * HD + c4]);
        }
        CP_COMMIT();
    };

    // ---- stage Q (128x64, pre-rounded) via cp.async ----
#pragma unroll
    for (int i = 0; i < 8; i++) {
        int c = t + i * 256;
        int row = c >> 4, c4 = (c & 15) * 4;
        cp16(&Qs[row * AST + c4], &Qp[(size_t)(q0 + row) * HD + c4]);
    }
    CP_COMMIT();
    stage_kv(0, 0);                       // prefetch KV tile 0 behind Q
    CP_WAIT(1);                           // Q ready; KV0 may be in flight
    __syncthreads();

    const int mrow = warp * 16 + gid;
    unsigned qa[8][4];
#pragma unroll
    for (int kf = 0; kf < 8; kf++) {
        qa[kf][0] = Qs[mrow * AST + kf * 8 + tig];
        qa[kf][1] = Qs[(mrow + 8) * AST + kf * 8 + tig];
        qa[kf][2] = Qs[mrow * AST + kf * 8 + tig + 4];
        qa[kf][3] = Qs[(mrow + 8) * AST + kf * 8 + tig + 4];
    }

    float ml0 = -1e30f, ml1 = -1e30f, l0 = 0.f, l1 = 0.f;
    float o[8][4] = {};

    const int row0g = q0 + warp * 16 + gid;
    const int row1g = row0g + 8;
    const int wrmin = q0 + warp * 16;
    const int wrmax = wrmin + 15;
    const int jmax  = q0 + 64;

    const int q2  = tig >> 1;                 // quad source sublane
    const int src1 = (lane & ~3) | q2;
    const int src2 = src1 + 2;
    const bool odd = (tig & 1);

    for (int j0 = 0; j0 <= jmax; j0 += 64) {
        const int buf = (j0 >> 6) & 1;
        if (j0 + 64 <= jmax) { stage_kv(buf ^ 1, j0 + 64); CP_WAIT(1); }
        else                 { CP_WAIT(0); }
        __syncthreads();

        if (j0 <= wrmax) {
            const unsigned* Ks = Ksb + buf * KBUF;
            const unsigned* Vs = Vsb + buf * VBUF;

            const bool needmask = (j0 + 63 > wrmin);
            const int gmax = needmask ? ((wrmax - j0) >> 3) : 7;  // <=7

            // ---- S = Q K^T (log2-scaled) on live groups only ----
            float s[8][4];
#pragma unroll
            for (int nf = 0; nf < 8; nf++) {
                if (nf <= gmax) {
                    s[nf][0] = 0.f; s[nf][1] = 0.f; s[nf][2] = 0.f; s[nf][3] = 0.f;
#pragma unroll
                    for (int kf = 0; kf < 8; kf++) {
                        unsigned b0 = Ks[(nf * 8 + gid) * KST + kf * 8 + tig];
                        unsigned b1 = Ks[(nf * 8 + gid) * KST + kf * 8 + tig + 4];
                        mma_tf32(s[nf], qa[kf][0], qa[kf][1], qa[kf][2], qa[kf][3], b0, b1);
                    }
                }
            }

            // ---- causal mask (diagonal-adjacent tiles only) ----
            if (needmask) {
#pragma unroll
                for (int nf = 0; nf < 8; nf++) {
                    if (nf <= gmax) {
                        int c = j0 + nf * 8 + 2 * tig;
                        if (c     > row0g) s[nf][0] = -1e30f;
                        if (c + 1 > row0g) s[nf][1] = -1e30f;
                        if (c     > row1g) s[nf][2] = -1e30f;
                        if (c + 1 > row1g) s[nf][3] = -1e30f;
                    }
                }
            }

            // ---- row max (base-2 domain) ----
            float mx0 = ml0, mx1 = ml1;
#pragma unroll
            for (int nf = 0; nf < 8; nf++) {
                if (nf <= gmax) {
                    mx0 = fmaxf(mx0, fmaxf(s[nf][0], s[nf][1]));
                    mx1 = fmaxf(mx1, fmaxf(s[nf][2], s[nf][3]));
                }
            }
            mx0 = fmaxf(mx0, __shfl_xor_sync(0xffffffffu, mx0, 1));
            mx0 = fmaxf(mx0, __shfl_xor_sync(0xffffffffu, mx0, 2));
            mx1 = fmaxf(mx1, __shfl_xor_sync(0xffffffffu, mx1, 1));
            mx1 = fmaxf(mx1, __shfl_xor_sync(0xffffffffu, mx1, 2));

            const float sc0 = ex2f(ml0 - mx0), sc1 = ex2f(ml1 - mx1);
            ml0 = mx0; ml1 = mx1;
#pragma unroll
            for (int nf = 0; nf < 8; nf++) {
                o[nf][0] *= sc0; o[nf][1] *= sc0;
                o[nf][2] *= sc1; o[nf][3] *= sc1;
            }

            // ---- per k8-group: exp -> in-register transpose -> PV MMA ----
            float sum0 = 0.f, sum1 = 0.f;
#pragma unroll
            for (int g = 0; g < 8; g++) {
                if (g <= gmax) {
                    float p0 = ex2f(s[g][0] - mx0);
                    float p1 = ex2f(s[g][1] - mx0);
                    float p2 = ex2f(s[g][2] - mx1);
                    float p3 = ex2f(s[g][3] - mx1);
                    sum0 += p0 + p1;
                    sum1 += p2 + p3;
                    p0 = f2tf32f(p0); p1 = f2tf32f(p1);
                    p2 = f2tf32f(p2); p3 = f2tf32f(p3);

                    // S fragment (rows gid/gid+8, cols 2tig,2tig+1) ->
                    // A fragment (cols tig, tig+4) via quad shuffles
                    float u00 = __shfl_sync(0xffffffffu, p0, src1);
                    float u01 = __shfl_sync(0xffffffffu, p1, src1);
                    float u10 = __shfl_sync(0xffffffffu, p2, src1);
                    float u11 = __shfl_sync(0xffffffffu, p3, src1);
                    float v00 = __shfl_sync(0xffffffffu, p0, src2);
                    float v01 = __shfl_sync(0xffffffffu, p1, src2);
                    float v10 = __shfl_sync(0xffffffffu, p2, src2);
                    float v11 = __shfl_sync(0xffffffffu, p3, src2);
                    unsigned pa0 = __float_as_uint(odd ? u01 : u00);
                    unsigned pa1 = __float_as_uint(odd ? u11 : u10);
                    unsigned pa2 = __float_as_uint(odd ? v01 : v00);
                    unsigned pa3 = __float_as_uint(odd ? v11 : v10);

#pragma unroll
                    for (int nf = 0; nf < 8; nf++) {
                        unsigned vb0 = Vs[(g * 8 + tig) * VST + nf * 8 + gid];
                        unsigned vb1 = Vs[(g * 8 + tig + 4) * VST + nf * 8 + gid];
                        mma_tf32(o[nf], pa0, pa1, pa2, pa3, vb0, vb1);
                    }
                }
            }

            sum0 += __shfl_xor_sync(0xffffffffu, sum0, 1);
            sum0 += __shfl_xor_sync(0xffffffffu, sum0, 2);
            sum1 += __shfl_xor_sync(0xffffffffu, sum1, 1);
            sum1 += __shfl_xor_sync(0xffffffffu, sum1, 2);
            l0 = l0 * sc0 + sum0;
            l1 = l1 * sc1 + sum1;
        }
        __syncthreads();
    }

    // ---- normalize + round + write attended [B*S, E] ----
    const float inv0 = 1.0f / l0, inv1 = 1.0f / l1;
#pragma unroll
    for (int nf = 0; nf < 8; nf++) {
        int col = h * HD + nf * 8 + 2 * tig;
        float2 v0 = make_float2(f2tf32f(o[nf][0] * inv0), f2tf32f(o[nf][1] * inv0));
        float2 v1 = make_float2(f2tf32f(o[nf][2] * inv1), f2tf32f(o[nf][3] * inv1));
        *(float2*)&g_Att[(size_t)(b * S_LEN + row0g) * E_DIM + col] = v0;
        *(float2*)&g_Att[(size_t)(b * S_LEN + row1g) * E_DIM + col] = v1;
    }
}

// ---------------------------------------------------------------------------
// Kernel 3: output projection. out[8192,768] = Att @ Wo + b_out.
// ---------------------------------------------------------------------------
__global__ __launch_bounds__(256) void out_gemm(
    const float* __restrict__ bias, float* __restrict__ out)
{
    extern __shared__ unsigned smg[];
    unsigned* Asb = smg;
    unsigned* Bsb = smg + 3 * GA_SZ;

    const int t    = threadIdx.x;
    const int lane = t & 31, warp = t >> 5;
    const int gid  = lane >> 2, tig = lane & 3;
    const int wm   = warp >> 2, wn = warp & 3;
    const int row0 = blockIdx.y * 128;
    const int col0 = blockIdx.x * 128;

    float acc[4][4][4] = {};

    auto stage = [&](int buf, int kk) {
        unsigned* A = Asb + buf * GA_SZ;
        unsigned* B = Bsb + buf * GB_SZ;
#pragma unroll
        for (int i = 0; i < 4; i++) {
            int c = t + i * 256;
            int rr = c >> 3, c4 = (c & 7) * 4;
            cp16(&A[rr * GA_ST + c4], &g_Att[(size_t)(row0 + rr) * E_DIM + kk + c4]);
        }
#pragma unroll
        for (int i = 0; i < 4; i++) {
            int c = t + i * 256;
            int rr = c >> 5, c4 = (c & 31) * 4;
            cp16(&B[rr * GB_ST + c4], &g_Wo[(size_t)(kk + rr) * E_DIM + col0 + c4]);
        }
        CP_COMMIT();
    };

    const int NT = E_DIM / 32;
    stage(0, 0);
    stage(1, 32);
    int buf = 0;
    for (int it = 0; it < NT; it++) {
        if (it + 2 < NT)      { stage((it + 2) % 3, (it + 2) * 32); CP_WAIT(2); }
        else if (it + 1 < NT) { CP_WAIT(1); }
        else                  { CP_WAIT(0); }
        __syncthreads();
        unsigned* A = Asb + buf * GA_SZ;
        unsigned* B = Bsb + buf * GB_SZ;
#pragma unroll
        for (int kf = 0; kf < 4; kf++) {
            unsigned a[4][4], b[4][2];
#pragma unroll
            for (int mf = 0; mf < 4; mf++) {
                int m = wm * 64 + mf * 16 + gid;
                a[mf][0] = A[m * GA_ST + kf * 8 + tig];
                a[mf][1] = A[(m + 8) * GA_ST + kf * 8 + tig];
                a[mf][2] = A[m * GA_ST + kf * 8 + tig + 4];
                a[mf][3] = A[(m + 8) * GA_ST + kf * 8 + tig + 4];
            }
#pragma unroll
            for (int nf = 0; nf < 4; nf++) {
                int n = wn * 32 + nf * 8 + gid;
                b[nf][0] = B[(kf * 8 + tig) * GB_ST + n];
                b[nf][1] = B[(kf * 8 + tig + 4) * GB_ST + n];
            }
#pragma unroll
            for (int mf = 0; mf < 4; mf++)
#pragma unroll
                for (int nf = 0; nf < 4; nf++)
                    mma_tf32(acc[mf][nf], a[mf][0], a[mf][1], a[mf][2], a[mf][3],
                             b[nf][0], b[nf][1]);
        }
        __syncthreads();
        buf = (buf + 1) % 3;
    }

#pragma unroll
    for (int nf = 0; nf < 4; nf++) {
        int c = col0 + wn * 32 + nf * 8 + 2 * tig;
        float b0v = bias[c], b1v = bias[c + 1];
#pragma unroll
        for (int mf = 0; mf < 4; mf++) {
#pragma unroll
            for (int rr = 0; rr < 2; rr++) {
                int m = row0 + wm * 64 + mf * 16 + gid + rr * 8;
                float2 vv;
                vv.x = acc[mf][nf][rr * 2]     + b0v;
                vv.y = acc[mf][nf][rr * 2 + 1] + b1v;
                *(float2*)&out[(size_t)m * E_DIM + c] = vv;
            }
        }
    }
}

// ---------------------------------------------------------------------------
extern "C" void kernel_launch(void* const* d_in, const int* in_sizes, int n_in,
                              void* d_out, int out_size)
{
    const float* x     = (const float*)d_in[0];
    const float* w_qkv = (const float*)d_in[1];
    const float* b_qkv = (const float*)d_in[2];
    const float* w_out = (const float*)d_in[3];
    const float* b_out = (const float*)d_in[4];
    float* out = (float*)d_out;

    cudaFuncSetAttribute(attn_kernel,
                         cudaFuncAttributeMaxDynamicSharedMemorySize, ATTN_SMEM);
    cudaFuncSetAttribute(qkv_gemm,
                         cudaFuncAttributeMaxDynamicSharedMemorySize, GEMM_SMEM);
    cudaFuncSetAttribute(out_gemm,
                         cudaFuncAttributeMaxDynamicSharedMemorySize, GEMM_SMEM);

    prepass<<<1024, 256>>>(x, w_qkv, w_out);

    dim3 g1(QKV_N / 128, NTOK / 128);     // (18, 64)
    qkv_gemm<<<g1, 256, GEMM_SMEM>>>(b_qkv);

    attn_kernel<<<NQB * NH * BATCH, 256, ATTN_SMEM>>>();   // 768, descending

    dim3 g3(E_DIM / 128, NTOK / 128);     // (6, 64)
    out_gemm<<<g3, 256, GEMM_SMEM>>>(b_out, out);
}

// round 7
// speedup vs baseline: 1.1046x; 1.1046x over previous
#include <cuda_runtime.h>

#define S_LEN  4096
#define BATCH  2
#define NH     12
#define HD     64
#define E_DIM  768
#define QKV_N  2304
#define NTOK   (BATCH * S_LEN)
#define NQB    (S_LEN / 128)          // 32 q-blocks per (b,h)

// Scratch (allocation-free rule: __device__ globals). tf32-pre-rounded.
__device__ float g_Q[(size_t)BATCH * NH * S_LEN * HD];   // pre-scaled by 0.125*log2e
__device__ float g_K[(size_t)BATCH * NH * S_LEN * HD];
__device__ float g_V[(size_t)BATCH * NH * S_LEN * HD];
__device__ float g_Att[(size_t)NTOK * E_DIM];            // attended, rounded

// ---------------------------------------------------------------------------
// helpers
// ---------------------------------------------------------------------------
__device__ __forceinline__ unsigned f2tf32(float f) {
    unsigned u;
    asm("cvt.rna.tf32.f32 %0, %1;" : "=r"(u) : "f"(f));
    return u;
}
__device__ __forceinline__ float f2tf32f(float f) {
    return __uint_as_float(f2tf32(f));
}
__device__ __forceinline__ unsigned u2tf32(unsigned raw) {   // raw fp32 bits -> tf32
    return f2tf32(__uint_as_float(raw));
}
__device__ __forceinline__ float ex2f(float x) {
    float y;
    asm("ex2.approx.f32 %0, %1;" : "=f"(y) : "f"(x));
    return y;
}

__device__ __forceinline__ void mma_tf32(float c[4],
    unsigned a0, unsigned a1, unsigned a2, unsigned a3,
    unsigned b0, unsigned b1)
{
    asm volatile(
        "mma.sync.aligned.m16n8k8.row.col.f32.tf32.tf32.f32 "
        "{%0,%1,%2,%3}, {%4,%5,%6,%7}, {%8,%9}, {%0,%1,%2,%3};\n"
        : "+f"(c[0]), "+f"(c[1]), "+f"(c[2]), "+f"(c[3])
        : "r"(a0), "r"(a1), "r"(a2), "r"(a3), "r"(b0), "r"(b1));
}

__device__ __forceinline__ void cp16(void* s, const void* g) {
    unsigned sa = (unsigned)__cvta_generic_to_shared(s);
    asm volatile("cp.async.cg.shared.global [%0], [%1], 16;\n" :: "r"(sa), "l"(g));
}
#define CP_COMMIT() asm volatile("cp.async.commit_group;\n")
#define CP_WAIT(N)  asm volatile("cp.async.wait_group %0;\n" :: "n"(N))

// scale folded into Q: 1/sqrt(64) * log2(e)
#define QSCALE 0.1803368801111204f

// ---------------------------------------------------------------------------
// GEMM common: 128x128 tile, BK=32, 3-stage cp.async, tf32 MMA.
// Raw fp32 staged; tf32 rounding applied at fragment build (same numerics
// as a separate pre-rounding pass, without the extra kernel + traffic).
// ---------------------------------------------------------------------------
#define GA_ST 36
#define GB_ST 136
#define GA_SZ (128 * GA_ST)
#define GB_SZ (32 * GB_ST)
#define GEMM_SMEM (3 * (GA_SZ + GB_SZ) * 4)

// ---------------------------------------------------------------------------
// Kernel 1: QKV projection. C[8192,2304] = x @ w_qkv + b, scatter to Q/K/V.
// ---------------------------------------------------------------------------
__global__ __launch_bounds__(256) void qkv_gemm(
    const float* __restrict__ x, const float* __restrict__ w,
    const float* __restrict__ bias)
{
    extern __shared__ unsigned smg[];
    unsigned* Asb = smg;                 // [3][128][GA_ST]
    unsigned* Bsb = smg + 3 * GA_SZ;     // [3][32][GB_ST]

    const int t    = threadIdx.x;
    const int lane = t & 31, warp = t >> 5;
    const int gid  = lane >> 2, tig = lane & 3;
    const int wm   = warp >> 2, wn = warp & 3;
    const int row0 = blockIdx.y * 128;
    const int col0 = blockIdx.x * 128;

    float acc[4][4][4] = {};

    auto stage = [&](int buf, int kk) {
        unsigned* A = Asb + buf * GA_SZ;
        unsigned* B = Bsb + buf * GB_SZ;
#pragma unroll
        for (int i = 0; i < 4; i++) {
            int c = t + i * 256;
            int rr = c >> 3, c4 = (c & 7) * 4;
            cp16(&A[rr * GA_ST + c4], &x[(size_t)(row0 + rr) * E_DIM + kk + c4]);
        }
#pragma unroll
        for (int i = 0; i < 4; i++) {
            int c = t + i * 256;
            int rr = c >> 5, c4 = (c & 31) * 4;
            cp16(&B[rr * GB_ST + c4], &w[(size_t)(kk + rr) * QKV_N + col0 + c4]);
        }
        CP_COMMIT();
    };

    const int NT = E_DIM / 32;   // 24
    stage(0, 0);
    stage(1, 32);
    int buf = 0;
    for (int it = 0; it < NT; it++) {
        if (it + 2 < NT)      { stage((it + 2) % 3, (it + 2) * 32); CP_WAIT(2); }
        else if (it + 1 < NT) { CP_WAIT(1); }
        else                  { CP_WAIT(0); }
        __syncthreads();
        unsigned* A = Asb + buf * GA_SZ;
        unsigned* B = Bsb + buf * GB_SZ;
#pragma unroll
        for (int kf = 0; kf < 4; kf++) {
            unsigned a[4][4], b[4][2];
#pragma unroll
            for (int mf = 0; mf < 4; mf++) {
                int m = wm * 64 + mf * 16 + gid;
                a[mf][0] = u2tf32(A[m * GA_ST + kf * 8 + tig]);
                a[mf][1] = u2tf32(A[(m + 8) * GA_ST + kf * 8 + tig]);
                a[mf][2] = u2tf32(A[m * GA_ST + kf * 8 + tig + 4]);
                a[mf][3] = u2tf32(A[(m + 8) * GA_ST + kf * 8 + tig + 4]);
            }
#pragma unroll
            for (int nf = 0; nf < 4; nf++) {
                int n = wn * 32 + nf * 8 + gid;
                b[nf][0] = u2tf32(B[(kf * 8 + tig) * GB_ST + n]);
                b[nf][1] = u2tf32(B[(kf * 8 + tig + 4) * GB_ST + n]);
            }
#pragma unroll
            for (int mf = 0; mf < 4; mf++)
#pragma unroll
                for (int nf = 0; nf < 4; nf++)
                    mma_tf32(acc[mf][nf], a[mf][0], a[mf][1], a[mf][2], a[mf][3],
                             b[nf][0], b[nf][1]);
        }
        __syncthreads();
        buf = (buf + 1) % 3;
    }

    // Epilogue: bias + tf32 round + scatter to Q/K/V [B,H,S,D]
    const int part = col0 / E_DIM;
    float* dst = (part == 0) ? g_Q : (part == 1 ? g_K : g_V);
    const float qs = (part == 0) ? QSCALE : 1.0f;

#pragma unroll
    for (int nf = 0; nf < 4; nf++) {
        int cg = col0 + wn * 32 + nf * 8 + 2 * tig;
        float b0v = bias[cg], b1v = bias[cg + 1];
        int c = cg % E_DIM;
        int h = c >> 6, d = c & 63;
#pragma unroll
        for (int mf = 0; mf < 4; mf++) {
#pragma unroll
            for (int rr = 0; rr < 2; rr++) {
                int m = row0 + wm * 64 + mf * 16 + gid + rr * 8;
                int bb = m >> 12, s = m & 4095;
                size_t o = ((size_t)(bb * NH + h) * S_LEN + s) * HD + d;
                float2 vv;
                vv.x = f2tf32f((acc[mf][nf][rr * 2]     + b0v) * qs);
                vv.y = f2tf32f((acc[mf][nf][rr * 2 + 1] + b1v) * qs);
                *(float2*)&dst[o] = vv;
            }
        }
    }
}

// ---------------------------------------------------------------------------
// Kernel 2: causal flash attention, tf32 MMA + log2-domain softmax.
// Double-buffered cp.async K/V, descending schedule, smem P round-trip.
// 256 threads = 8 warps, each warp owns 16 query rows.  (R5 structure)
// ---------------------------------------------------------------------------
#define AST 68
#define KST 68
#define VST 72
#define KBUF (64 * KST)
#define VBUF (64 * VST)
#define ATTN_SMEM ((2 * KBUF + 2 * VBUF + 128 * AST) * 4)

__global__ __launch_bounds__(256) void attn_kernel()
{
    extern __shared__ unsigned sm[];
    unsigned* Ksb = sm;                       // [2][64][KST]
    unsigned* Vsb = sm + 2 * KBUF;            // [2][64][VST]
    unsigned* Ps  = sm + 2 * KBUF + 2 * VBUF; // [128][AST] (Q staging + P)

    const int t    = threadIdx.x;
    const int lane = t & 31, warp = t >> 5;
    const int gid  = lane >> 2, tig = lane & 3;

    // descending-size schedule: biggest q-blocks first
    const int r  = blockIdx.x;
    const int qb = (NQB - 1) - r / (NH * BATCH);
    const int hb = r % (NH * BATCH);
    const int h  = hb % NH;
    const int b  = hb / NH;
    const int q0 = qb * 128;

    const size_t base = (size_t)(b * NH + h) * S_LEN * HD;
    const float* Qp = g_Q + base;
    const float* Kp = g_K + base;
    const float* Vp = g_V + base;

    auto stage_kv = [&](int buf, int j0) {
        unsigned* K = Ksb + buf * KBUF;
        unsigned* V = Vsb + buf * VBUF;
#pragma unroll
        for (int i = 0; i < 4; i++) {
            int c = t + i * 256;
            int row = c >> 4, c4 = (c & 15) * 4;
            cp16(&K[row * KST + c4], &Kp[(size_t)(j0 + row) * HD + c4]);
            cp16(&V[row * VST + c4], &Vp[(size_t)(j0 + row) * HD + c4]);
        }
        CP_COMMIT();
    };

    // ---- stage Q (128x64, pre-rounded) via cp.async into Ps ----
#pragma unroll
    for (int i = 0; i < 8; i++) {
        int c = t + i * 256;
        int row = c >> 4, c4 = (c & 15) * 4;
        cp16(&Ps[row * AST + c4], &Qp[(size_t)(q0 + row) * HD + c4]);
    }
    CP_COMMIT();
    stage_kv(0, 0);                       // prefetch KV tile 0 behind Q
    CP_WAIT(1);                           // Q ready; KV0 may be in flight
    __syncthreads();

    const int mrow = warp * 16 + gid;
    unsigned qa[8][4];
#pragma unroll
    for (int kf = 0; kf < 8; kf++) {
        qa[kf][0] = Ps[mrow * AST + kf * 8 + tig];
        qa[kf][1] = Ps[(mrow + 8) * AST + kf * 8 + tig];
        qa[kf][2] = Ps[mrow * AST + kf * 8 + tig + 4];
        qa[kf][3] = Ps[(mrow + 8) * AST + kf * 8 + tig + 4];
    }

    float ml0 = -1e30f, ml1 = -1e30f, l0 = 0.f, l1 = 0.f;
    float o[8][4] = {};

    const int row0g = q0 + warp * 16 + gid;
    const int row1g = row0g + 8;
    const int wrmin = q0 + warp * 16;
    const int wrmax = wrmin + 15;
    const int jmax  = q0 + 64;

    for (int j0 = 0; j0 <= jmax; j0 += 64) {
        const int buf = (j0 >> 6) & 1;
        if (j0 + 64 <= jmax) { stage_kv(buf ^ 1, j0 + 64); CP_WAIT(1); }
        else                 { CP_WAIT(0); }
        __syncthreads();

        if (j0 <= wrmax) {
            const unsigned* Ks = Ksb + buf * KBUF;
            const unsigned* Vs = Vsb + buf * VBUF;

            // ---- S = Q K^T (log2-scaled: Q pre-scaled by 0.125*log2e) ----
            float s[8][4] = {};
#pragma unroll
            for (int kf = 0; kf < 8; kf++) {
#pragma unroll
                for (int nf = 0; nf < 8; nf++) {
                    unsigned b0 = Ks[(nf * 8 + gid) * KST + kf * 8 + tig];
                    unsigned b1 = Ks[(nf * 8 + gid) * KST + kf * 8 + tig + 4];
                    mma_tf32(s[nf], qa[kf][0], qa[kf][1], qa[kf][2], qa[kf][3], b0, b1);
                }
            }

            // ---- causal mask (only near the diagonal) ----
            if (j0 + 63 > wrmin) {
#pragma unroll
                for (int nf = 0; nf < 8; nf++) {
                    int c = j0 + nf * 8 + 2 * tig;
                    if (c     > row0g) s[nf][0] = -1e30f;
                    if (c + 1 > row0g) s[nf][1] = -1e30f;
                    if (c     > row1g) s[nf][2] = -1e30f;
                    if (c + 1 > row1g) s[nf][3] = -1e30f;
                }
            }

            // ---- online softmax, base-2 ----
            float mx0 = ml0, mx1 = ml1;
#pragma unroll
            for (int nf = 0; nf < 8; nf++) {
                mx0 = fmaxf(mx0, fmaxf(s[nf][0], s[nf][1]));
                mx1 = fmaxf(mx1, fmaxf(s[nf][2], s[nf][3]));
            }
            mx0 = fmaxf(mx0, __shfl_xor_sync(0xffffffffu, mx0, 1));
            mx0 = fmaxf(mx0, __shfl_xor_sync(0xffffffffu, mx0, 2));
            mx1 = fmaxf(mx1, __shfl_xor_sync(0xffffffffu, mx1, 1));
            mx1 = fmaxf(mx1, __shfl_xor_sync(0xffffffffu, mx1, 2));

            float sc0 = ex2f(ml0 - mx0), sc1 = ex2f(ml1 - mx1);
            float sum0 = 0.f, sum1 = 0.f;
#pragma unroll
            for (int nf = 0; nf < 8; nf++) {
                s[nf][0] = ex2f(s[nf][0] - mx0);
                s[nf][1] = ex2f(s[nf][1] - mx0);
                s[nf][2] = ex2f(s[nf][2] - mx1);
                s[nf][3] = ex2f(s[nf][3] - mx1);
                sum0 += s[nf][0] + s[nf][1];
                sum1 += s[nf][2] + s[nf][3];
            }
            sum0 += __shfl_xor_sync(0xffffffffu, sum0, 1);
            sum0 += __shfl_xor_sync(0xffffffffu, sum0, 2);
            sum1 += __shfl_xor_sync(0xffffffffu, sum1, 1);
            sum1 += __shfl_xor_sync(0xffffffffu, sum1, 2);

            l0 = l0 * sc0 + sum0;  l1 = l1 * sc1 + sum1;
            ml0 = mx0;             ml1 = mx1;

#pragma unroll
            for (int nf = 0; nf < 8; nf++) {
                o[nf][0] *= sc0; o[nf][1] *= sc0;
                o[nf][2] *= sc1; o[nf][3] *= sc1;
            }

            // ---- store P (tf32) to warp-private rows of Ps ----
#pragma unroll
            for (int nf = 0; nf < 8; nf++) {
                int cc = nf * 8 + 2 * tig;
                Ps[mrow * AST + cc]           = f2tf32(s[nf][0]);
                Ps[mrow * AST + cc + 1]       = f2tf32(s[nf][1]);
                Ps[(mrow + 8) * AST + cc]     = f2tf32(s[nf][2]);
                Ps[(mrow + 8) * AST + cc + 1] = f2tf32(s[nf][3]);
            }
            __syncwarp();

            // ---- O += P V ----
#pragma unroll
            for (int kf = 0; kf < 8; kf++) {
                unsigned pa0 = Ps[mrow * AST + kf * 8 + tig];
                unsigned pa1 = Ps[(mrow + 8) * AST + kf * 8 + tig];
                unsigned pa2 = Ps[mrow * AST + kf * 8 + tig + 4];
                unsigned pa3 = Ps[(mrow + 8) * AST + kf * 8 + tig + 4];
#pragma unroll
                for (int nf = 0; nf < 8; nf++) {
                    unsigned vb0 = Vs[(kf * 8 + tig) * VST + nf * 8 + gid];
                    unsigned vb1 = Vs[(kf * 8 + tig + 4) * VST + nf * 8 + gid];
                    mma_tf32(o[nf], pa0, pa1, pa2, pa3, vb0, vb1);
                }
            }
        }
        __syncthreads();
    }

    // ---- normalize + round + write attended [B*S, E] ----
    const float inv0 = 1.0f / l0, inv1 = 1.0f / l1;
#pragma unroll
    for (int nf = 0; nf < 8; nf++) {
        int col = h * HD + nf * 8 + 2 * tig;
        float2 v0 = make_float2(f2tf32f(o[nf][0] * inv0), f2tf32f(o[nf][1] * inv0));
        float2 v1 = make_float2(f2tf32f(o[nf][2] * inv1), f2tf32f(o[nf][3] * inv1));
        *(float2*)&g_Att[(size_t)(b * S_LEN + row0g) * E_DIM + col] = v0;
        *(float2*)&g_Att[(size_t)(b * S_LEN + row1g) * E_DIM + col] = v1;
    }
}

// ---------------------------------------------------------------------------
// Kernel 3: output projection. out[8192,768] = g_Att @ w_out + b_out.
// g_Att already rounded; w_out rounded at fragment build.
// ---------------------------------------------------------------------------
__global__ __launch_bounds__(256) void out_gemm(
    const float* __restrict__ w, const float* __restrict__ bias,
    float* __restrict__ out)
{
    extern __shared__ unsigned smg[];
    unsigned* Asb = smg;
    unsigned* Bsb = smg + 3 * GA_SZ;

    const int t    = threadIdx.x;
    const int lane = t & 31, warp = t >> 5;
    const int gid  = lane >> 2, tig = lane & 3;
    const int wm   = warp >> 2, wn = warp & 3;
    const int row0 = blockIdx.y * 128;
    const int col0 = blockIdx.x * 128;

    float acc[4][4][4] = {};

    auto stage = [&](int buf, int kk) {
        unsigned* A = Asb + buf * GA_SZ;
        unsigned* B = Bsb + buf * GB_SZ;
#pragma unroll
        for (int i = 0; i < 4; i++) {
            int c = t + i * 256;
            int rr = c >> 3, c4 = (c & 7) * 4;
            cp16(&A[rr * GA_ST + c4], &g_Att[(size_t)(row0 + rr) * E_DIM + kk + c4]);
        }
#pragma unroll
        for (int i = 0; i < 4; i++) {
            int c = t + i * 256;
            int rr = c >> 5, c4 = (c & 31) * 4;
            cp16(&B[rr * GB_ST + c4], &w[(size_t)(kk + rr) * E_DIM + col0 + c4]);
        }
        CP_COMMIT();
    };

    const int NT = E_DIM / 32;
    stage(0, 0);
    stage(1, 32);
    int buf = 0;
    for (int it = 0; it < NT; it++) {
        if (it + 2 < NT)      { stage((it + 2) % 3, (it + 2) * 32); CP_WAIT(2); }
        else if (it + 1 < NT) { CP_WAIT(1); }
        else                  { CP_WAIT(0); }
        __syncthreads();
        unsigned* A = Asb + buf * GA_SZ;
        unsigned* B = Bsb + buf * GB_SZ;
#pragma unroll
        for (int kf = 0; kf < 4; kf++) {
            unsigned a[4][4], b[4][2];
#pragma unroll
            for (int mf = 0; mf < 4; mf++) {
                int m = wm * 64 + mf * 16 + gid;
                a[mf][0] = A[m * GA_ST + kf * 8 + tig];        // g_Att pre-rounded
                a[mf][1] = A[(m + 8) * GA_ST + kf * 8 + tig];
                a[mf][2] = A[m * GA_ST + kf * 8 + tig + 4];
                a[mf][3] = A[(m + 8) * GA_ST + kf * 8 + tig + 4];
            }
#pragma unroll
            for (int nf = 0; nf < 4; nf++) {
                int n = wn * 32 + nf * 8 + gid;
                b[nf][0] = u2tf32(B[(kf * 8 + tig) * GB_ST + n]);
                b[nf][1] = u2tf32(B[(kf * 8 + tig + 4) * GB_ST + n]);
            }
#pragma unroll
            for (int mf = 0; mf < 4; mf++)
#pragma unroll
                for (int nf = 0; nf < 4; nf++)
                    mma_tf32(acc[mf][nf], a[mf][0], a[mf][1], a[mf][2], a[mf][3],
                             b[nf][0], b[nf][1]);
        }
        __syncthreads();
        buf = (buf + 1) % 3;
    }

#pragma unroll
    for (int nf = 0; nf < 4; nf++) {
        int c = col0 + wn * 32 + nf * 8 + 2 * tig;
        float b0v = bias[c], b1v = bias[c + 1];
#pragma unroll
        for (int mf = 0; mf < 4; mf++) {
#pragma unroll
            for (int rr = 0; rr < 2; rr++) {
                int m = row0 + wm * 64 + mf * 16 + gid + rr * 8;
                float2 vv;
                vv.x = acc[mf][nf][rr * 2]     + b0v;
                vv.y = acc[mf][nf][rr * 2 + 1] + b1v;
                *(float2*)&out[(size_t)m * E_DIM + c] = vv;
            }
        }
    }
}

// ---------------------------------------------------------------------------
extern "C" void kernel_launch(void* const* d_in, const int* in_sizes, int n_in,
                              void* d_out, int out_size)
{
    const float* x     = (const float*)d_in[0];
    const float* w_qkv = (const float*)d_in[1];
    const float* b_qkv = (const float*)d_in[2];
    const float* w_out = (const float*)d_in[3];
    const float* b_out = (const float*)d_in[4];
    float* out = (float*)d_out;

    cudaFuncSetAttribute(attn_kernel,
                         cudaFuncAttributeMaxDynamicSharedMemorySize, ATTN_SMEM);
    cudaFuncSetAttribute(qkv_gemm,
                         cudaFuncAttributeMaxDynamicSharedMemorySize, GEMM_SMEM);
    cudaFuncSetAttribute(out_gemm,
                         cudaFuncAttributeMaxDynamicSharedMemorySize, GEMM_SMEM);

    dim3 g1(QKV_N / 128, NTOK / 128);     // (18, 64)
    qkv_gemm<<<g1, 256, GEMM_SMEM>>>(x, w_qkv, b_qkv);

    attn_kernel<<<NQB * NH * BATCH, 256, ATTN_SMEM>>>();   // 768, descending

    dim3 g3(E_DIM / 128, NTOK / 128);     // (6, 64)
    out_gemm<<<g3, 256, GEMM_SMEM>>>(w_out, b_out, out);
}

// round 12
// speedup vs baseline: 1.3300x; 1.2040x over previous
#include <cuda_runtime.h>
#include <cuda_fp16.h>

#define S_LEN  4096
#define BATCH  2
#define NH     12
#define HD     64
#define E_DIM  768
#define QKV_N  2304
#define NTOK   (BATCH * S_LEN)
#define NQB    (S_LEN / 128)          // 32 q-blocks per (b,h)

// Scratch (allocation-free rule: __device__ globals).
__device__ float g_Q[(size_t)BATCH * NH * S_LEN * HD];   // tf32, pre-scaled 0.125*log2e
__device__ float g_K[(size_t)BATCH * NH * S_LEN * HD];   // tf32
__device__ __half g_Vt[(size_t)BATCH * NH * HD * S_LEN]; // fp16, [b][h][d][s]
__device__ float g_Att[(size_t)NTOK * E_DIM];            // attended, tf32-rounded
__device__ float g_Xr[(size_t)NTOK * E_DIM];             // rounded x
__device__ float g_Wq[(size_t)E_DIM * QKV_N];            // rounded w_qkv
__device__ float g_Wo[(size_t)E_DIM * E_DIM];            // rounded w_out

// ---------------------------------------------------------------------------
// helpers
// ---------------------------------------------------------------------------
__device__ __forceinline__ unsigned f2tf32(float f) {
    unsigned u;
    asm("cvt.rna.tf32.f32 %0, %1;" : "=r"(u) : "f"(f));
    return u;
}
__device__ __forceinline__ float f2tf32f(float f) {
    return __uint_as_float(f2tf32(f));
}
__device__ __forceinline__ float ex2f(float x) {
    float y;
    asm("ex2.approx.f32 %0, %1;" : "=f"(y) : "f"(x));
    return y;
}

__device__ __forceinline__ void mma_tf32(float c[4],
    unsigned a0, unsigned a1, unsigned a2, unsigned a3,
    unsigned b0, unsigned b1)
{
    asm volatile(
        "mma.sync.aligned.m16n8k8.row.col.f32.tf32.tf32.f32 "
        "{%0,%1,%2,%3}, {%4,%5,%6,%7}, {%8,%9}, {%0,%1,%2,%3};\n"
        : "+f"(c[0]), "+f"(c[1]), "+f"(c[2]), "+f"(c[3])
        : "r"(a0), "r"(a1), "r"(a2), "r"(a3), "r"(b0), "r"(b1));
}

__device__ __forceinline__ void mma_f16(float c[4],
    unsigned a0, unsigned a1, unsigned a2, unsigned a3,
    unsigned b0, unsigned b1)
{
    asm volatile(
        "mma.sync.aligned.m16n8k16.row.col.f32.f16.f16.f32 "
        "{%0,%1,%2,%3}, {%4,%5,%6,%7}, {%8,%9}, {%0,%1,%2,%3};\n"
        : "+f"(c[0]), "+f"(c[1]), "+f"(c[2]), "+f"(c[3])
        : "r"(a0), "r"(a1), "r"(a2), "r"(a3), "r"(b0), "r"(b1));
}

__device__ __forceinline__ void cp16(void* s, const void* g) {
    unsigned sa = (unsigned)__cvta_generic_to_shared(s);
    asm volatile("cp.async.cg.shared.global [%0], [%1], 16;\n" :: "r"(sa), "l"(g));
}
#define CP_COMMIT() asm volatile("cp.async.commit_group;\n")
#define CP_WAIT(N)  asm volatile("cp.async.wait_group %0;\n" :: "n"(N))

// scale folded into Q: 1/sqrt(64) * log2(e)
#define QSCALE 0.1803368801111204f

// ---------------------------------------------------------------------------
// Kernel 0: pre-round inputs to tf32 (cvt-free cp.async GEMM mainloops)
// ---------------------------------------------------------------------------
__global__ void prepass(const float* __restrict__ x,
                        const float* __restrict__ wq,
                        const float* __restrict__ wo)
{
    const int stride = gridDim.x * blockDim.x;
    const int tid = blockIdx.x * blockDim.x + threadIdx.x;
    const int nx = NTOK * E_DIM / 4, nq = E_DIM * QKV_N / 4, no = E_DIM * E_DIM / 4;
    for (int i = tid; i < nx; i += stride) {
        float4 v = ((const float4*)x)[i];
        ((float4*)g_Xr)[i] = make_float4(f2tf32f(v.x), f2tf32f(v.y), f2tf32f(v.z), f2tf32f(v.w));
    }
    for (int i = tid; i < nq; i += stride) {
        float4 v = ((const float4*)wq)[i];
        ((float4*)g_Wq)[i] = make_float4(f2tf32f(v.x), f2tf32f(v.y), f2tf32f(v.z), f2tf32f(v.w));
    }
    for (int i = tid; i < no; i += stride) {
        float4 v = ((const float4*)wo)[i];
        ((float4*)g_Wo)[i] = make_float4(f2tf32f(v.x), f2tf32f(v.y), f2tf32f(v.z), f2tf32f(v.w));
    }
}

// ---------------------------------------------------------------------------
// GEMM common: 128x128 tile, BK=32, 3-stage cp.async, tf32 MMA, no in-loop cvt
// ---------------------------------------------------------------------------
#define GA_ST 36
#define GB_ST 136
#define GA_SZ (128 * GA_ST)
#define GB_SZ (32 * GB_ST)
#define GEMM_SMEM (3 * (GA_SZ + GB_SZ) * 4)

// ---------------------------------------------------------------------------
// Kernel 1: QKV projection. C[8192,2304] = Xr @ Wq + b, scatter to Q/K/Vt.
// ---------------------------------------------------------------------------
__global__ __launch_bounds__(256) void qkv_gemm(const float* __restrict__ bias)
{
    extern __shared__ unsigned smg[];
    unsigned* Asb = smg;                 // [3][128][GA_ST]
    unsigned* Bsb = smg + 3 * GA_SZ;     // [3][32][GB_ST]

    const int t    = threadIdx.x;
    const int lane = t & 31, warp = t >> 5;
    const int gid  = lane >> 2, tig = lane & 3;
    const int wm   = warp >> 2, wn = warp & 3;
    const int row0 = blockIdx.y * 128;
    const int col0 = blockIdx.x * 128;

    float acc[4][4][4] = {};

    auto stage = [&](int buf, int kk) {
        unsigned* A = Asb + buf * GA_SZ;
        unsigned* B = Bsb + buf * GB_SZ;
#pragma unroll
        for (int i = 0; i < 4; i++) {
            int c = t + i * 256;
            int rr = c >> 3, c4 = (c & 7) * 4;
            cp16(&A[rr * GA_ST + c4], &g_Xr[(size_t)(row0 + rr) * E_DIM + kk + c4]);
        }
#pragma unroll
        for (int i = 0; i < 4; i++) {
            int c = t + i * 256;
            int rr = c >> 5, c4 = (c & 31) * 4;
            cp16(&B[rr * GB_ST + c4], &g_Wq[(size_t)(kk + rr) * QKV_N + col0 + c4]);
        }
        CP_COMMIT();
    };

    const int NT = E_DIM / 32;   // 24
    stage(0, 0);
    stage(1, 32);
    int buf = 0;
    for (int it = 0; it < NT; it++) {
        if (it + 2 < NT)      { stage((it + 2) % 3, (it + 2) * 32); CP_WAIT(2); }
        else if (it + 1 < NT) { CP_WAIT(1); }
        else                  { CP_WAIT(0); }
        __syncthreads();
        unsigned* A = Asb + buf * GA_SZ;
        unsigned* B = Bsb + buf * GB_SZ;
#pragma unroll
        for (int kf = 0; kf < 4; kf++) {
            unsigned a[4][4], b[4][2];
#pragma unroll
            for (int mf = 0; mf < 4; mf++) {
                int m = wm * 64 + mf * 16 + gid;
                a[mf][0] = A[m * GA_ST + kf * 8 + tig];
                a[mf][1] = A[(m + 8) * GA_ST + kf * 8 + tig];
                a[mf][2] = A[m * GA_ST + kf * 8 + tig + 4];
                a[mf][3] = A[(m + 8) * GA_ST + kf * 8 + tig + 4];
            }
#pragma unroll
            for (int nf = 0; nf < 4; nf++) {
                int n = wn * 32 + nf * 8 + gid;
                b[nf][0] = B[(kf * 8 + tig) * GB_ST + n];
                b[nf][1] = B[(kf * 8 + tig + 4) * GB_ST + n];
            }
#pragma unroll
            for (int mf = 0; mf < 4; mf++)
#pragma unroll
                for (int nf = 0; nf < 4; nf++)
                    mma_tf32(acc[mf][nf], a[mf][0], a[mf][1], a[mf][2], a[mf][3],
                             b[nf][0], b[nf][1]);
        }
        __syncthreads();
        buf = (buf + 1) % 3;
    }

    // Epilogue: bias + scatter. Q/K: tf32-rounded fp32 [B,H,S,D].
    //           V: fp16, TRANSPOSED [B,H,D,S] for the attn PV B-fragment.
    const int part = col0 / E_DIM;

    if (part < 2) {
        float* dst = (part == 0) ? g_Q : g_K;
        const float qs = (part == 0) ? QSCALE : 1.0f;
#pragma unroll
        for (int nf = 0; nf < 4; nf++) {
            int cg = col0 + wn * 32 + nf * 8 + 2 * tig;
            float b0v = bias[cg], b1v = bias[cg + 1];
            int c = cg % E_DIM;
            int h = c >> 6, d = c & 63;
#pragma unroll
            for (int mf = 0; mf < 4; mf++) {
#pragma unroll
                for (int rr = 0; rr < 2; rr++) {
                    int m = row0 + wm * 64 + mf * 16 + gid + rr * 8;
                    int bb = m >> 12, s = m & 4095;
                    size_t o = ((size_t)(bb * NH + h) * S_LEN + s) * HD + d;
                    float2 vv;
                    vv.x = f2tf32f((acc[mf][nf][rr * 2]     + b0v) * qs);
                    vv.y = f2tf32f((acc[mf][nf][rr * 2 + 1] + b1v) * qs);
                    *(float2*)&dst[o] = vv;
                }
            }
        }
    } else {
#pragma unroll
        for (int nf = 0; nf < 4; nf++) {
            int cg = col0 + wn * 32 + nf * 8 + 2 * tig;
            float b0v = bias[cg], b1v = bias[cg + 1];
            int c = cg % E_DIM;
            int h = c >> 6, d = c & 63;
#pragma unroll
            for (int mf = 0; mf < 4; mf++) {
#pragma unroll
                for (int rr = 0; rr < 2; rr++) {
                    int m = row0 + wm * 64 + mf * 16 + gid + rr * 8;
                    int bb = m >> 12, s = m & 4095;
                    __half* vb =
                        g_Vt + ((size_t)(bb * NH + h) * HD + d) * S_LEN + s;
                    vb[0]     = __float2half_rn(acc[mf][nf][rr * 2]     + b0v);
                    vb[S_LEN] = __float2half_rn(acc[mf][nf][rr * 2 + 1] + b1v);
                }
            }
        }
    }
}

// ---------------------------------------------------------------------------
// Kernel 2: causal flash attention. QK^T tf32, softmax base-2, PV fp16 k16
// with zero-copy S->A fragment reuse. Double-buffered cp.async K + Vt.
// ---------------------------------------------------------------------------
#define AST 68
#define KST 68
#define KBUF (64 * KST)
#define VTW  36                          // Vt row stride in 32-bit words (72 fp16)
#define VTB  (64 * VTW * 4)              // one Vt buffer in bytes (9216)
#define ATTN_SMEM (2 * KBUF * 4 + 2 * VTB + 128 * AST * 4)

__global__ __launch_bounds__(256, 2) void attn_kernel()
{
    extern __shared__ unsigned sm[];
    unsigned* Ksb = sm;                        // [2][64][KST] tf32
    char*     Vtb = (char*)(sm + 2 * KBUF);    // [2][64 d][72 fp16]
    unsigned* Ps  = (unsigned*)(Vtb + 2 * VTB);// [128][AST] (Q staging)

    const int t    = threadIdx.x;
    const int lane = t & 31, warp = t >> 5;
    const int gid  = lane >> 2, tig = lane & 3;

    // descending-size schedule: biggest q-blocks first
    const int r  = blockIdx.x;
    const int qb = (NQB - 1) - r / (NH * BATCH);
    const int hb = r % (NH * BATCH);
    const int h  = hb % NH;
    const int b  = hb / NH;
    const int q0 = qb * 128;

    const size_t base = (size_t)(b * NH + h) * S_LEN * HD;
    const float* Qp = g_Q + base;
    const float* Kp = g_K + base;
    const __half* Vtp = g_Vt + (size_t)(b * NH + h) * HD * S_LEN;

    auto stage_kv = [&](int buf, int j0) {
        unsigned* K = Ksb + buf * KBUF;
        char* V = Vtb + buf * VTB;
#pragma unroll
        for (int i = 0; i < 4; i++) {
            int c = t + i * 256;
            int row = c >> 4, c4 = (c & 15) * 4;
            cp16(&K[row * KST + c4], &Kp[(size_t)(j0 + row) * HD + c4]);
        }
#pragma unroll
        for (int i = 0; i < 2; i++) {           // Vt: 64 d-rows x 128B
            int c = t + i * 256;
            int row = c >> 3, ch = c & 7;
            cp16(V + row * (VTW * 4) + ch * 16,
                 Vtp + (size_t)row * S_LEN + j0 + ch * 8);
        }
        CP_COMMIT();
    };

    // ---- stage Q (128x64, pre-rounded tf32) ----
#pragma unroll
    for (int i = 0; i < 8; i++) {
        int c = t + i * 256;
        int row = c >> 4, c4 = (c & 15) * 4;
        cp16(&Ps[row * AST + c4], &Qp[(size_t)(q0 + row) * HD + c4]);
    }
    CP_COMMIT();
    stage_kv(0, 0);
    CP_WAIT(1);                           // Q ready; KV0 in flight
    __syncthreads();

    const int mrow = warp * 16 + gid;
    unsigned qa[8][4];
#pragma unroll
    for (int kf = 0; kf < 8; kf++) {
        qa[kf][0] = Ps[mrow * AST + kf * 8 + tig];
        qa[kf][1] = Ps[(mrow + 8) * AST + kf * 8 + tig];
        qa[kf][2] = Ps[mrow * AST + kf * 8 + tig + 4];
        qa[kf][3] = Ps[(mrow + 8) * AST + kf * 8 + tig + 4];
    }

    float ml0 = -1e30f, ml1 = -1e30f, l0 = 0.f, l1 = 0.f;
    float o[8][4] = {};

    const int row0g = q0 + warp * 16 + gid;
    const int row1g = row0g + 8;
    const int wrmin = q0 + warp * 16;
    const int wrmax = wrmin + 15;
    const int jmax  = q0 + 64;

    for (int j0 = 0; j0 <= jmax; j0 += 64) {
        const int buf = (j0 >> 6) & 1;
        if (j0 + 64 <= jmax) { stage_kv(buf ^ 1, j0 + 64); CP_WAIT(1); }
        else                 { CP_WAIT(0); }
        __syncthreads();

        if (j0 <= wrmax) {
            const unsigned* Ks = Ksb + buf * KBUF;
            const unsigned* Vt32 = (const unsigned*)(Vtb + buf * VTB);

            // ---- S = Q K^T (tf32, log2-scaled) ----
            float s[8][4] = {};
#pragma unroll
            for (int kf = 0; kf < 8; kf++) {
#pragma unroll
                for (int nf = 0; nf < 8; nf++) {
                    unsigned b0 = Ks[(nf * 8 + gid) * KST + kf * 8 + tig];
                    unsigned b1 = Ks[(nf * 8 + gid) * KST + kf * 8 + tig + 4];
                    mma_tf32(s[nf], qa[kf][0], qa[kf][1], qa[kf][2], qa[kf][3], b0, b1);
                }
            }

            // ---- causal mask (diagonal-adjacent tiles only) ----
            if (j0 + 63 > wrmin) {
#pragma unroll
                for (int nf = 0; nf < 8; nf++) {
                    int c = j0 + nf * 8 + 2 * tig;
                    if (c     > row0g) s[nf][0] = -1e30f;
                    if (c + 1 > row0g) s[nf][1] = -1e30f;
                    if (c     > row1g) s[nf][2] = -1e30f;
                    if (c + 1 > row1g) s[nf][3] = -1e30f;
                }
            }

            // ---- row max (base-2 domain) ----
            float mx0 = ml0, mx1 = ml1;
#pragma unroll
            for (int nf = 0; nf < 8; nf++) {
                mx0 = fmaxf(mx0, fmaxf(s[nf][0], s[nf][1]));
                mx1 = fmaxf(mx1, fmaxf(s[nf][2], s[nf][3]));
            }
            mx0 = fmaxf(mx0, __shfl_xor_sync(0xffffffffu, mx0, 1));
            mx0 = fmaxf(mx0, __shfl_xor_sync(0xffffffffu, mx0, 2));
            mx1 = fmaxf(mx1, __shfl_xor_sync(0xffffffffu, mx1, 1));
            mx1 = fmaxf(mx1, __shfl_xor_sync(0xffffffffu, mx1, 2));

            const float sc0 = ex2f(ml0 - mx0), sc1 = ex2f(ml1 - mx1);
            ml0 = mx0; ml1 = mx1;
#pragma unroll
            for (int nf = 0; nf < 8; nf++) {
                o[nf][0] *= sc0; o[nf][1] *= sc0;
                o[nf][2] *= sc1; o[nf][3] *= sc1;
            }

            // ---- exp, pack P to fp16 A-fragments (ZERO data movement),
            //      and sum the ROUNDED values for exact normalization ----
            unsigned pA[4][4];           // [k16 group][a0..a3]
            float sum0 = 0.f, sum1 = 0.f;
#pragma unroll
            for (int nf = 0; nf < 8; nf++) {
                float p0 = ex2f(s[nf][0] - mx0);
                float p1 = ex2f(s[nf][1] - mx0);
                float p2 = ex2f(s[nf][2] - mx1);
                float p3 = ex2f(s[nf][3] - mx1);
                __half2 h01 = __floats2half2_rn(p0, p1); // .x=p0 in low half
                __half2 h23 = __floats2half2_rn(p2, p3);
                float2 f01 = __half22float2(h01);
                float2 f23 = __half22float2(h23);
                sum0 += f01.x + f01.y;
                sum1 += f23.x + f23.y;
                int g = nf >> 1;
                if ((nf & 1) == 0) {
                    pA[g][0] = *(unsigned*)&h01;   // row gid,   cols 2tig,2tig+1
                    pA[g][1] = *(unsigned*)&h23;   // row gid+8
                } else {
                    pA[g][2] = *(unsigned*)&h01;   // row gid,   cols +8
                    pA[g][3] = *(unsigned*)&h23;   // row gid+8, cols +8
                }
            }

            sum0 += __shfl_xor_sync(0xffffffffu, sum0, 1);
            sum0 += __shfl_xor_sync(0xffffffffu, sum0, 2);
            sum1 += __shfl_xor_sync(0xffffffffu, sum1, 1);
            sum1 += __shfl_xor_sync(0xffffffffu, sum1, 2);
            l0 = l0 * sc0 + sum0;
            l1 = l1 * sc1 + sum1;

            // ---- O += P V  (fp16 m16n8k16; B = Vt[d][s] fp16x2 direct) ----
#pragma unroll
            for (int g = 0; g < 4; g++) {
#pragma unroll
                for (int nf = 0; nf < 8; nf++) {
                    unsigned vb0 = Vt32[(nf * 8 + gid) * VTW + g * 8 + tig];
                    unsigned vb1 = Vt32[(nf * 8 + gid) * VTW + g * 8 + tig + 4];
                    mma_f16(o[nf], pA[g][0], pA[g][1], pA[g][2], pA[g][3], vb0, vb1);
                }
            }
        }
        __syncthreads();
    }

    // ---- normalize + round + write attended [B*S, E] ----
    const float inv0 = 1.0f / l0, inv1 = 1.0f / l1;
#pragma unroll
    for (int nf = 0; nf < 8; nf++) {
        int col = h * HD + nf * 8 + 2 * tig;
        float2 v0 = make_float2(f2tf32f(o[nf][0] * inv0), f2tf32f(o[nf][1] * inv0));
        float2 v1 = make_float2(f2tf32f(o[nf][2] * inv1), f2tf32f(o[nf][3] * inv1));
        *(float2*)&g_Att[(size_t)(b * S_LEN + row0g) * E_DIM + col] = v0;
        *(float2*)&g_Att[(size_t)(b * S_LEN + row1g) * E_DIM + col] = v1;
    }
}

// ---------------------------------------------------------------------------
// Kernel 3: output projection. out[8192,768] = g_Att @ Wo + b_out.
// ---------------------------------------------------------------------------
__global__ __launch_bounds__(256) void out_gemm(
    const float* __restrict__ bias, float* __restrict__ out)
{
    extern __shared__ unsigned smg[];
    unsigned* Asb = smg;
    unsigned* Bsb = smg + 3 * GA_SZ;

    const int t    = threadIdx.x;
    const int lane = t & 31, warp = t >> 5;
    const int gid  = lane >> 2, tig = lane & 3;
    const int wm   = warp >> 2, wn = warp & 3;
    const int row0 = blockIdx.y * 128;
    const int col0 = blockIdx.x * 128;

    float acc[4][4][4] = {};

    auto stage = [&](int buf, int kk) {
        unsigned* A = Asb + buf * GA_SZ;
        unsigned* B = Bsb + buf * GB_SZ;
#pragma unroll
        for (int i = 0; i < 4; i++) {
            int c = t + i * 256;
            int rr = c >> 3, c4 = (c & 7) * 4;
            cp16(&A[rr * GA_ST + c4], &g_Att[(size_t)(row0 + rr) * E_DIM + kk + c4]);
        }
#pragma unroll
        for (int i = 0; i < 4; i++) {
            int c = t + i * 256;
            int rr = c >> 5, c4 = (c & 31) * 4;
            cp16(&B[rr * GB_ST + c4], &g_Wo[(size_t)(kk + rr) * E_DIM + col0 + c4]);
        }
        CP_COMMIT();
    };

    const int NT = E_DIM / 32;
    stage(0, 0);
    stage(1, 32);
    int buf = 0;
    for (int it = 0; it < NT; it++) {
        if (it + 2 < NT)      { stage((it + 2) % 3, (it + 2) * 32); CP_WAIT(2); }
        else if (it + 1 < NT) { CP_WAIT(1); }
        else                  { CP_WAIT(0); }
        __syncthreads();
        unsigned* A = Asb + buf * GA_SZ;
        unsigned* B = Bsb + buf * GB_SZ;
#pragma unroll
        for (int kf = 0; kf < 4; kf++) {
            unsigned a[4][4], b[4][2];
#pragma unroll
            for (int mf = 0; mf < 4; mf++) {
                int m = wm * 64 + mf * 16 + gid;
                a[mf][0] = A[m * GA_ST + kf * 8 + tig];
                a[mf][1] = A[(m + 8) * GA_ST + kf * 8 + tig];
                a[mf][2] = A[m * GA_ST + kf * 8 + tig + 4];
                a[mf][3] = A[(m + 8) * GA_ST + kf * 8 + tig + 4];
            }
#pragma unroll
            for (int nf = 0; nf < 4; nf++) {
                int n = wn * 32 + nf * 8 + gid;
                b[nf][0] = B[(kf * 8 + tig) * GB_ST + n];
                b[nf][1] = B[(kf * 8 + tig + 4) * GB_ST + n];
            }
#pragma unroll
            for (int mf = 0; mf < 4; mf++)
#pragma unroll
                for (int nf = 0; nf < 4; nf++)
                    mma_tf32(acc[mf][nf], a[mf][0], a[mf][1], a[mf][2], a[mf][3],
                             b[nf][0], b[nf][1]);
        }
        __syncthreads();
        buf = (buf + 1) % 3;
    }

#pragma unroll
    for (int nf = 0; nf < 4; nf++) {
        int c = col0 + wn * 32 + nf * 8 + 2 * tig;
        float b0v = bias[c], b1v = bias[c + 1];
#pragma unroll
        for (int mf = 0; mf < 4; mf++) {
#pragma unroll
            for (int rr = 0; rr < 2; rr++) {
                int m = row0 + wm * 64 + mf * 16 + gid + rr * 8;
                float2 vv;
                vv.x = acc[mf][nf][rr * 2]     + b0v;
                vv.y = acc[mf][nf][rr * 2 + 1] + b1v;
                *(float2*)&out[(size_t)m * E_DIM + c] = vv;
            }
        }
    }
}

// ---------------------------------------------------------------------------
extern "C" void kernel_launch(void* const* d_in, const int* in_sizes, int n_in,
                              void* d_out, int out_size)
{
    const float* x     = (const float*)d_in[0];
    const float* w_qkv = (const float*)d_in[1];
    const float* b_qkv = (const float*)d_in[2];
    const float* w_out = (const float*)d_in[3];
    const float* b_out = (const float*)d_in[4];
    float* out = (float*)d_out;

    cudaFuncSetAttribute(attn_kernel,
                         cudaFuncAttributeMaxDynamicSharedMemorySize, ATTN_SMEM);
    cudaFuncSetAttribute(qkv_gemm,
                         cudaFuncAttributeMaxDynamicSharedMemorySize, GEMM_SMEM);
    cudaFuncSetAttribute(out_gemm,
                         cudaFuncAttributeMaxDynamicSharedMemorySize, GEMM_SMEM);

    prepass<<<1024, 256>>>(x, w_qkv, w_out);

    dim3 g1(QKV_N / 128, NTOK / 128);     // (18, 64)
    qkv_gemm<<<g1, 256, GEMM_SMEM>>>(b_qkv);

    attn_kernel<<<NQB * NH * BATCH, 256, ATTN_SMEM>>>();   // 768, descending

    dim3 g3(E_DIM / 128, NTOK / 128);     // (6, 64)
    out_gemm<<<g3, 256, GEMM_SMEM>>>(b_out, out);
}

// round 15
// speedup vs baseline: 1.5320x; 1.1519x over previous
#include <cuda_runtime.h>
#include <cuda_fp16.h>

#define S_LEN  4096
#define BATCH  2
#define NH     12
#define HD     64
#define E_DIM  768
#define QKV_N  2304
#define NTOK   (BATCH * S_LEN)
#define NQB    (S_LEN / 128)          // 32 q-blocks per (b,h)

// Scratch (allocation-free rule: __device__ globals).
__device__ float  g_Xr[(size_t)NTOK * E_DIM];            // tf32-rounded x
__device__ float  g_Wq[(size_t)E_DIM * QKV_N];           // tf32-rounded w_qkv
__device__ float  g_Wo[(size_t)E_DIM * E_DIM];           // tf32-rounded w_out
__device__ __half g_Q[(size_t)BATCH * NH * S_LEN * HD];  // fp16, pre-scaled 0.125*log2e
__device__ __half g_K[(size_t)BATCH * NH * S_LEN * HD];  // fp16
__device__ __half g_Vt[(size_t)BATCH * NH * HD * S_LEN]; // fp16, [b][h][d][s]
__device__ float  g_Att[(size_t)NTOK * E_DIM];           // attended, tf32-rounded

// ---------------------------------------------------------------------------
// helpers
// ---------------------------------------------------------------------------
__device__ __forceinline__ unsigned f2tf32(float f) {
    unsigned u;
    asm("cvt.rna.tf32.f32 %0, %1;" : "=r"(u) : "f"(f));
    return u;
}
__device__ __forceinline__ float f2tf32f(float f) {
    return __uint_as_float(f2tf32(f));
}
__device__ __forceinline__ float ex2f(float x) {
    float y;
    asm("ex2.approx.f32 %0, %1;" : "=f"(y) : "f"(x));
    return y;
}

__device__ __forceinline__ void mma_tf32(float c[4],
    unsigned a0, unsigned a1, unsigned a2, unsigned a3,
    unsigned b0, unsigned b1)
{
    asm volatile(
        "mma.sync.aligned.m16n8k8.row.col.f32.tf32.tf32.f32 "
        "{%0,%1,%2,%3}, {%4,%5,%6,%7}, {%8,%9}, {%0,%1,%2,%3};\n"
        : "+f"(c[0]), "+f"(c[1]), "+f"(c[2]), "+f"(c[3])
        : "r"(a0), "r"(a1), "r"(a2), "r"(a3), "r"(b0), "r"(b1));
}

__device__ __forceinline__ void mma_f16(float c[4],
    unsigned a0, unsigned a1, unsigned a2, unsigned a3,
    unsigned b0, unsigned b1)
{
    asm volatile(
        "mma.sync.aligned.m16n8k16.row.col.f32.f16.f16.f32 "
        "{%0,%1,%2,%3}, {%4,%5,%6,%7}, {%8,%9}, {%0,%1,%2,%3};\n"
        : "+f"(c[0]), "+f"(c[1]), "+f"(c[2]), "+f"(c[3])
        : "r"(a0), "r"(a1), "r"(a2), "r"(a3), "r"(b0), "r"(b1));
}

__device__ __forceinline__ void cp16(void* s, const void* g) {
    unsigned sa = (unsigned)__cvta_generic_to_shared(s);
    asm volatile("cp.async.cg.shared.global [%0], [%1], 16;\n" :: "r"(sa), "l"(g));
}
#define CP_COMMIT() asm volatile("cp.async.commit_group;\n")
#define CP_WAIT(N)  asm volatile("cp.async.wait_group %0;\n" :: "n"(N))

// scale folded into Q: 1/sqrt(64) * log2(e)
#define QSCALE 0.1803368801111204f

// ---------------------------------------------------------------------------
// Kernel 0: pre-round inputs to tf32 (cvt-free cp.async GEMM mainloops)
// ---------------------------------------------------------------------------
__global__ void prepass(const float* __restrict__ x,
                        const float* __restrict__ wq,
                        const float* __restrict__ wo)
{
    const int stride = gridDim.x * blockDim.x;
    const int tid = blockIdx.x * blockDim.x + threadIdx.x;
    const int nx = NTOK * E_DIM / 4, nq = E_DIM * QKV_N / 4, no = E_DIM * E_DIM / 4;
    for (int i = tid; i < nx; i += stride) {
        float4 v = ((const float4*)x)[i];
        ((float4*)g_Xr)[i] = make_float4(f2tf32f(v.x), f2tf32f(v.y), f2tf32f(v.z), f2tf32f(v.w));
    }
    for (int i = tid; i < nq; i += stride) {
        float4 v = ((const float4*)wq)[i];
        ((float4*)g_Wq)[i] = make_float4(f2tf32f(v.x), f2tf32f(v.y), f2tf32f(v.z), f2tf32f(v.w));
    }
    for (int i = tid; i < no; i += stride) {
        float4 v = ((const float4*)wo)[i];
        ((float4*)g_Wo)[i] = make_float4(f2tf32f(v.x), f2tf32f(v.y), f2tf32f(v.z), f2tf32f(v.w));
    }
}

// ---------------------------------------------------------------------------
// GEMM common (R12-validated): 128x128 tile, BK=32, 3-stage cp.async, tf32.
// ---------------------------------------------------------------------------
#define GA_ST 36
#define GB_ST 136
#define GA_SZ (128 * GA_ST)
#define GB_SZ (32 * GB_ST)
#define GEMM_SMEM (3 * (GA_SZ + GB_SZ) * 4)

// ---------------------------------------------------------------------------
// Kernel 1: QKV projection (tf32 MMA, R12-validated mainloop).
// Epilogue: Q/K fp16 [B,H,S,D] (Q pre-scaled), V fp16 transposed [B,H,D,S].
// ---------------------------------------------------------------------------
__global__ __launch_bounds__(256) void qkv_gemm(const float* __restrict__ bias)
{
    extern __shared__ unsigned smg[];
    unsigned* Asb = smg;                 // [3][128][GA_ST]
    unsigned* Bsb = smg + 3 * GA_SZ;     // [3][32][GB_ST]

    const int t    = threadIdx.x;
    const int lane = t & 31, warp = t >> 5;
    const int gid  = lane >> 2, tig = lane & 3;
    const int wm   = warp >> 2, wn = warp & 3;
    const int row0 = blockIdx.y * 128;
    const int col0 = blockIdx.x * 128;

    float acc[4][4][4] = {};

    auto stage = [&](int buf, int kk) {
        unsigned* A = Asb + buf * GA_SZ;
        unsigned* B = Bsb + buf * GB_SZ;
#pragma unroll
        for (int i = 0; i < 4; i++) {
            int c = t + i * 256;
            int rr = c >> 3, c4 = (c & 7) * 4;
            cp16(&A[rr * GA_ST + c4], &g_Xr[(size_t)(row0 + rr) * E_DIM + kk + c4]);
        }
#pragma unroll
        for (int i = 0; i < 4; i++) {
            int c = t + i * 256;
            int rr = c >> 5, c4 = (c & 31) * 4;
            cp16(&B[rr * GB_ST + c4], &g_Wq[(size_t)(kk + rr) * QKV_N + col0 + c4]);
        }
        CP_COMMIT();
    };

    const int NT = E_DIM / 32;   // 24
    stage(0, 0);
    stage(1, 32);
    int buf = 0;
    for (int it = 0; it < NT; it++) {
        if (it + 2 < NT)      { stage((it + 2) % 3, (it + 2) * 32); CP_WAIT(2); }
        else if (it + 1 < NT) { CP_WAIT(1); }
        else                  { CP_WAIT(0); }
        __syncthreads();
        unsigned* A = Asb + buf * GA_SZ;
        unsigned* B = Bsb + buf * GB_SZ;
#pragma unroll
        for (int kf = 0; kf < 4; kf++) {
            unsigned a[4][4], b[4][2];
#pragma unroll
            for (int mf = 0; mf < 4; mf++) {
                int m = wm * 64 + mf * 16 + gid;
                a[mf][0] = A[m * GA_ST + kf * 8 + tig];
                a[mf][1] = A[(m + 8) * GA_ST + kf * 8 + tig];
                a[mf][2] = A[m * GA_ST + kf * 8 + tig + 4];
                a[mf][3] = A[(m + 8) * GA_ST + kf * 8 + tig + 4];
            }
#pragma unroll
            for (int nf = 0; nf < 4; nf++) {
                int n = wn * 32 + nf * 8 + gid;
                b[nf][0] = B[(kf * 8 + tig) * GB_ST + n];
                b[nf][1] = B[(kf * 8 + tig + 4) * GB_ST + n];
            }
#pragma unroll
            for (int mf = 0; mf < 4; mf++)
#pragma unroll
                for (int nf = 0; nf < 4; nf++)
                    mma_tf32(acc[mf][nf], a[mf][0], a[mf][1], a[mf][2], a[mf][3],
                             b[nf][0], b[nf][1]);
        }
        __syncthreads();
        buf = (buf + 1) % 3;
    }

    // Epilogue: bias + scatter. Q/K: fp16 [B,H,S,D]. V: fp16 [B,H,D,S].
    const int part = col0 / E_DIM;

    if (part < 2) {
        __half* dst = (part == 0) ? g_Q : g_K;
        const float qs = (part == 0) ? QSCALE : 1.0f;
#pragma unroll
        for (int nf = 0; nf < 4; nf++) {
            int cg = col0 + wn * 32 + nf * 8 + 2 * tig;
            float b0v = bias[cg], b1v = bias[cg + 1];
            int c = cg % E_DIM;
            int h = c >> 6, d = c & 63;
#pragma unroll
            for (int mf = 0; mf < 4; mf++) {
#pragma unroll
                for (int rr = 0; rr < 2; rr++) {
                    int m = row0 + wm * 64 + mf * 16 + gid + rr * 8;
                    int bb = m >> 12, s = m & 4095;
                    size_t o = ((size_t)(bb * NH + h) * S_LEN + s) * HD + d;
                    *(__half2*)&dst[o] = __floats2half2_rn(
                        (acc[mf][nf][rr * 2]     + b0v) * qs,
                        (acc[mf][nf][rr * 2 + 1] + b1v) * qs);
                }
            }
        }
    } else {
#pragma unroll
        for (int nf = 0; nf < 4; nf++) {
            int cg = col0 + wn * 32 + nf * 8 + 2 * tig;
            float b0v = bias[cg], b1v = bias[cg + 1];
            int c = cg % E_DIM;
            int h = c >> 6, d = c & 63;
#pragma unroll
            for (int mf = 0; mf < 4; mf++) {
#pragma unroll
                for (int rr = 0; rr < 2; rr++) {
                    int m = row0 + wm * 64 + mf * 16 + gid + rr * 8;
                    int bb = m >> 12, s = m & 4095;
                    __half* vb =
                        g_Vt + ((size_t)(bb * NH + h) * HD + d) * S_LEN + s;
                    vb[0]     = __float2half_rn(acc[mf][nf][rr * 2]     + b0v);
                    vb[S_LEN] = __float2half_rn(acc[mf][nf][rr * 2 + 1] + b1v);
                }
            }
        }
    }
}

// ---------------------------------------------------------------------------
// Kernel 2: causal flash attention. fp16 QK^T (k16) + fp16 PV (k16),
// base-2 softmax, zero-copy P fragments. Double-buffered cp.async K+Vt.
// Structure identical to R12 except Q/K are fp16.
// ---------------------------------------------------------------------------
#define QW   36                          // Q row stride, words (64 data + pad)
#define KW   36                          // K row stride, words
#define VTW  36                          // Vt row stride, words
#define KBUFW (64 * KW)
#define VBUFW (64 * VTW)
#define ATTN_SMEM ((128 * QW + 2 * KBUFW + 2 * VBUFW) * 4)   // 55296 B

__global__ __launch_bounds__(256, 2) void attn_kernel()
{
    extern __shared__ unsigned sm[];
    unsigned* Qs  = sm;                        // [128][QW]  fp16
    unsigned* Ksb = sm + 128 * QW;             // [2][64][KW] fp16
    unsigned* Vsb = Ksb + 2 * KBUFW;           // [2][64][VTW] fp16

    const int t    = threadIdx.x;
    const int lane = t & 31, warp = t >> 5;
    const int gid  = lane >> 2, tig = lane & 3;

    // descending-size schedule: biggest q-blocks first
    const int r  = blockIdx.x;
    const int qb = (NQB - 1) - r / (NH * BATCH);
    const int hb = r % (NH * BATCH);
    const int h  = hb % NH;
    const int b  = hb / NH;
    const int q0 = qb * 128;

    const size_t base = (size_t)(b * NH + h) * S_LEN * HD;
    const __half* Qp = g_Q + base;
    const __half* Kp = g_K + base;
    const __half* Vtp = g_Vt + (size_t)(b * NH + h) * HD * S_LEN;

    auto stage_kv = [&](int buf, int j0) {
        unsigned* K = Ksb + buf * KBUFW;
        unsigned* V = Vsb + buf * VBUFW;
#pragma unroll
        for (int i = 0; i < 2; i++) {            // K: 64 rows x 128B
            int c = t + i * 256;
            int row = c >> 3, seg = c & 7;
            cp16(&K[row * KW + seg * 4], &Kp[(size_t)(j0 + row) * HD + seg * 8]);
        }
#pragma unroll
        for (int i = 0; i < 2; i++) {            // Vt: 64 d-rows x 128B
            int c = t + i * 256;
            int row = c >> 3, seg = c & 7;
            cp16(&V[row * VTW + seg * 4], &Vtp[(size_t)row * S_LEN + j0 + seg * 8]);
        }
        CP_COMMIT();
    };

    // ---- stage Q (128 rows x 128B fp16) ----
#pragma unroll
    for (int i = 0; i < 4; i++) {
        int c = t + i * 256;
        int row = c >> 3, seg = c & 7;
        cp16(&Qs[row * QW + seg * 4], &Qp[(size_t)(q0 + row) * HD + seg * 8]);
    }
    CP_COMMIT();
    stage_kv(0, 0);
    CP_WAIT(1);                           // Q ready; KV0 in flight
    __syncthreads();

    const int mrow = warp * 16 + gid;
    unsigned qa[4][4];
#pragma unroll
    for (int kf = 0; kf < 4; kf++) {
        qa[kf][0] = Qs[mrow * QW + kf * 8 + tig];
        qa[kf][1] = Qs[(mrow + 8) * QW + kf * 8 + tig];
        qa[kf][2] = Qs[mrow * QW + kf * 8 + tig + 4];
        qa[kf][3] = Qs[(mrow + 8) * QW + kf * 8 + tig + 4];
    }

    float ml0 = -1e30f, ml1 = -1e30f, l0 = 0.f, l1 = 0.f;
    float o[8][4] = {};

    const int row0g = q0 + warp * 16 + gid;
    const int row1g = row0g + 8;
    const int wrmin = q0 + warp * 16;
    const int wrmax = wrmin + 15;
    const int jmax  = q0 + 64;

    for (int j0 = 0; j0 <= jmax; j0 += 64) {
        const int buf = (j0 >> 6) & 1;
        if (j0 + 64 <= jmax) { stage_kv(buf ^ 1, j0 + 64); CP_WAIT(1); }
        else                 { CP_WAIT(0); }
        __syncthreads();

        if (j0 <= wrmax) {
            const unsigned* Ks = Ksb + buf * KBUFW;
            const unsigned* Vt32 = Vsb + buf * VBUFW;

            // ---- S = Q K^T (fp16 k16, log2-scaled) ----
            float s[8][4] = {};
#pragma unroll
            for (int kf = 0; kf < 4; kf++) {
#pragma unroll
                for (int nf = 0; nf < 8; nf++) {
                    unsigned b0 = Ks[(nf * 8 + gid) * KW + kf * 8 + tig];
                    unsigned b1 = Ks[(nf * 8 + gid) * KW + kf * 8 + tig + 4];
                    mma_f16(s[nf], qa[kf][0], qa[kf][1], qa[kf][2], qa[kf][3], b0, b1);
                }
            }

            // ---- causal mask (diagonal-adjacent tiles only) ----
            if (j0 + 63 > wrmin) {
#pragma unroll
                for (int nf = 0; nf < 8; nf++) {
                    int c = j0 + nf * 8 + 2 * tig;
                    if (c     > row0g) s[nf][0] = -1e30f;
                    if (c + 1 > row0g) s[nf][1] = -1e30f;
                    if (c     > row1g) s[nf][2] = -1e30f;
                    if (c + 1 > row1g) s[nf][3] = -1e30f;
                }
            }

            // ---- row max (base-2 domain) ----
            float mx0 = ml0, mx1 = ml1;
#pragma unroll
            for (int nf = 0; nf < 8; nf++) {
                mx0 = fmaxf(mx0, fmaxf(s[nf][0], s[nf][1]));
                mx1 = fmaxf(mx1, fmaxf(s[nf][2], s[nf][3]));
            }
            mx0 = fmaxf(mx0, __shfl_xor_sync(0xffffffffu, mx0, 1));
            mx0 = fmaxf(mx0, __shfl_xor_sync(0xffffffffu, mx0, 2));
            mx1 = fmaxf(mx1, __shfl_xor_sync(0xffffffffu, mx1, 1));
            mx1 = fmaxf(mx1, __shfl_xor_sync(0xffffffffu, mx1, 2));

            const float sc0 = ex2f(ml0 - mx0), sc1 = ex2f(ml1 - mx1);
            ml0 = mx0; ml1 = mx1;
#pragma unroll
            for (int nf = 0; nf < 8; nf++) {
                o[nf][0] *= sc0; o[nf][1] *= sc0;
                o[nf][2] *= sc1; o[nf][3] *= sc1;
            }

            // ---- exp, pack P to fp16 A-fragments; sum ROUNDED P ----
            unsigned pA[4][4];           // [k16 group][a0..a3]
            float sum0 = 0.f, sum1 = 0.f;
#pragma unroll
            for (int nf = 0; nf < 8; nf++) {
                float p0 = ex2f(s[nf][0] - mx0);
                float p1 = ex2f(s[nf][1] - mx0);
                float p2 = ex2f(s[nf][2] - mx1);
                float p3 = ex2f(s[nf][3] - mx1);
                __half2 h01 = __floats2half2_rn(p0, p1);
                __half2 h23 = __floats2half2_rn(p2, p3);
                float2 f01 = __half22float2(h01);
                float2 f23 = __half22float2(h23);
                sum0 += f01.x + f01.y;
                sum1 += f23.x + f23.y;
                int g = nf >> 1;
                if ((nf & 1) == 0) {
                    pA[g][0] = *(unsigned*)&h01;
                    pA[g][1] = *(unsigned*)&h23;
                } else {
                    pA[g][2] = *(unsigned*)&h01;
                    pA[g][3] = *(unsigned*)&h23;
                }
            }

            sum0 += __shfl_xor_sync(0xffffffffu, sum0, 1);
            sum0 += __shfl_xor_sync(0xffffffffu, sum0, 2);
            sum1 += __shfl_xor_sync(0xffffffffu, sum1, 1);
            sum1 += __shfl_xor_sync(0xffffffffu, sum1, 2);
            l0 = l0 * sc0 + sum0;
            l1 = l1 * sc1 + sum1;

            // ---- O += P V  (fp16 k16; B = Vt[d][s] direct) ----
#pragma unroll
            for (int g = 0; g < 4; g++) {
#pragma unroll
                for (int nf = 0; nf < 8; nf++) {
                    unsigned vb0 = Vt32[(nf * 8 + gid) * VTW + g * 8 + tig];
                    unsigned vb1 = Vt32[(nf * 8 + gid) * VTW + g * 8 + tig + 4];
                    mma_f16(o[nf], pA[g][0], pA[g][1], pA[g][2], pA[g][3], vb0, vb1);
                }
            }
        }
        __syncthreads();
    }

    // ---- normalize + tf32-round + write attended (fp32) [B*S, E] ----
    const float inv0 = 1.0f / l0, inv1 = 1.0f / l1;
#pragma unroll
    for (int nf = 0; nf < 8; nf++) {
        int col = h * HD + nf * 8 + 2 * tig;
        float2 v0 = make_float2(f2tf32f(o[nf][0] * inv0), f2tf32f(o[nf][1] * inv0));
        float2 v1 = make_float2(f2tf32f(o[nf][2] * inv1), f2tf32f(o[nf][3] * inv1));
        *(float2*)&g_Att[(size_t)(b * S_LEN + row0g) * E_DIM + col] = v0;
        *(float2*)&g_Att[(size_t)(b * S_LEN + row1g) * E_DIM + col] = v1;
    }
}

// ---------------------------------------------------------------------------
// Kernel 3: output projection (tf32 MMA, R12-validated).
// ---------------------------------------------------------------------------
__global__ __launch_bounds__(256) void out_gemm(
    const float* __restrict__ bias, float* __restrict__ out)
{
    extern __shared__ unsigned smg[];
    unsigned* Asb = smg;
    unsigned* Bsb = smg + 3 * GA_SZ;

    const int t    = threadIdx.x;
    const int lane = t & 31, warp = t >> 5;
    const int gid  = lane >> 2, tig = lane & 3;
    const int wm   = warp >> 2, wn = warp & 3;
    const int row0 = blockIdx.y * 128;
    const int col0 = blockIdx.x * 128;

    float acc[4][4][4] = {};

    auto stage = [&](int buf, int kk) {
        unsigned* A = Asb + buf * GA_SZ;
        unsigned* B = Bsb + buf * GB_SZ;
#pragma unroll
        for (int i = 0; i < 4; i++) {
            int c = t + i * 256;
            int rr = c >> 3, c4 = (c & 7) * 4;
            cp16(&A[rr * GA_ST + c4], &g_Att[(size_t)(row0 + rr) * E_DIM + kk + c4]);
        }
#pragma unroll
        for (int i = 0; i < 4; i++) {
            int c = t + i * 256;
            int rr = c >> 5, c4 = (c & 31) * 4;
            cp16(&B[rr * GB_ST + c4], &g_Wo[(size_t)(kk + rr) * E_DIM + col0 + c4]);
        }
        CP_COMMIT();
    };

    const int NT = E_DIM / 32;
    stage(0, 0);
    stage(1, 32);
    int buf = 0;
    for (int it = 0; it < NT; it++) {
        if (it + 2 < NT)      { stage((it + 2) % 3, (it + 2) * 32); CP_WAIT(2); }
        else if (it + 1 < NT) { CP_WAIT(1); }
        else                  { CP_WAIT(0); }
        __syncthreads();
        unsigned* A = Asb + buf * GA_SZ;
        unsigned* B = Bsb + buf * GB_SZ;
#pragma unroll
        for (int kf = 0; kf < 4; kf++) {
            unsigned a[4][4], b[4][2];
#pragma unroll
            for (int mf = 0; mf < 4; mf++) {
                int m = wm * 64 + mf * 16 + gid;
                a[mf][0] = A[m * GA_ST + kf * 8 + tig];
                a[mf][1] = A[(m + 8) * GA_ST + kf * 8 + tig];
                a[mf][2] = A[m * GA_ST + kf * 8 + tig + 4];
                a[mf][3] = A[(m + 8) * GA_ST + kf * 8 + tig + 4];
            }
#pragma unroll
            for (int nf = 0; nf < 4; nf++) {
                int n = wn * 32 + nf * 8 + gid;
                b[nf][0] = B[(kf * 8 + tig) * GB_ST + n];
                b[nf][1] = B[(kf * 8 + tig + 4) * GB_ST + n];
            }
#pragma unroll
            for (int mf = 0; mf < 4; mf++)
#pragma unroll
                for (int nf = 0; nf < 4; nf++)
                    mma_tf32(acc[mf][nf], a[mf][0], a[mf][1], a[mf][2], a[mf][3],
                             b[nf][0], b[nf][1]);
        }
        __syncthreads();
        buf = (buf + 1) % 3;
    }

#pragma unroll
    for (int nf = 0; nf < 4; nf++) {
        int c = col0 + wn * 32 + nf * 8 + 2 * tig;
        float b0v = bias[c], b1v = bias[c + 1];
#pragma unroll
        for (int mf = 0; mf < 4; mf++) {
#pragma unroll
            for (int rr = 0; rr < 2; rr++) {
                int m = row0 + wm * 64 + mf * 16 + gid + rr * 8;
                float2 vv;
                vv.x = acc[mf][nf][rr * 2]     + b0v;
                vv.y = acc[mf][nf][rr * 2 + 1] + b1v;
                *(float2*)&out[(size_t)m * E_DIM + c] = vv;
            }
        }
    }
}

// ---------------------------------------------------------------------------
extern "C" void kernel_launch(void* const* d_in, const int* in_sizes, int n_in,
                              void* d_out, int out_size)
{
    const float* x     = (const float*)d_in[0];
    const float* w_qkv = (const float*)d_in[1];
    const float* b_qkv = (const float*)d_in[2];
    const float* w_out = (const float*)d_in[3];
    const float* b_out = (const float*)d_in[4];
    float* out = (float*)d_out;

    cudaFuncSetAttribute(attn_kernel,
                         cudaFuncAttributeMaxDynamicSharedMemorySize, ATTN_SMEM);
    cudaFuncSetAttribute(qkv_gemm,
                         cudaFuncAttributeMaxDynamicSharedMemorySize, GEMM_SMEM);
    cudaFuncSetAttribute(out_gemm,
                         cudaFuncAttributeMaxDynamicSharedMemorySize, GEMM_SMEM);

    prepass<<<1024, 256>>>(x, w_qkv, w_out);

    dim3 g1(QKV_N / 128, NTOK / 128);     // (18, 64)
    qkv_gemm<<<g1, 256, GEMM_SMEM>>>(b_qkv);

    attn_kernel<<<NQB * NH * BATCH, 256, ATTN_SMEM>>>();   // 768, descending

    dim3 g3(E_DIM / 128, NTOK / 128);     // (6, 64)
    out_gemm<<<g3, 256, GEMM_SMEM>>>(b_out, out);
}

// round 16
// speedup vs baseline: 1.5762x; 1.0289x over previous
#include <cuda_runtime.h>
#include <cuda_fp16.h>

#define S_LEN  4096
#define BATCH  2
#define NH     12
#define HD     64
#define E_DIM  768
#define QKV_N  2304
#define NTOK   (BATCH * S_LEN)
#define NQB    (S_LEN / 128)          // 32 q-blocks per (b,h)

// Scratch (allocation-free rule: __device__ globals).
__device__ float  g_Xr[(size_t)NTOK * E_DIM];            // tf32-rounded x
__device__ float  g_Wq[(size_t)E_DIM * QKV_N];           // tf32-rounded w_qkv
__device__ float  g_Wo[(size_t)E_DIM * E_DIM];           // tf32-rounded w_out
__device__ __half g_Q[(size_t)BATCH * NH * S_LEN * HD];  // fp16, pre-scaled 0.125*log2e
__device__ __half g_K[(size_t)BATCH * NH * S_LEN * HD];  // fp16
__device__ __half g_Vt[(size_t)BATCH * NH * HD * S_LEN]; // fp16, [b][h][d][s]
__device__ float  g_Att[(size_t)NTOK * E_DIM];           // attended, tf32-rounded

// ---------------------------------------------------------------------------
// helpers
// ---------------------------------------------------------------------------
__device__ __forceinline__ unsigned f2tf32(float f) {
    unsigned u;
    asm("cvt.rna.tf32.f32 %0, %1;" : "=r"(u) : "f"(f));
    return u;
}
__device__ __forceinline__ float f2tf32f(float f) {
    return __uint_as_float(f2tf32(f));
}
__device__ __forceinline__ float ex2f(float x) {
    float y;
    asm("ex2.approx.f32 %0, %1;" : "=f"(y) : "f"(x));
    return y;
}
__device__ __forceinline__ unsigned ex2_h2(unsigned x) {   // f16x2 2^x
    unsigned y;
    asm("ex2.approx.f16x2 %0, %1;" : "=r"(y) : "r"(x));
    return y;
}

__device__ __forceinline__ void mma_tf32(float c[4],
    unsigned a0, unsigned a1, unsigned a2, unsigned a3,
    unsigned b0, unsigned b1)
{
    asm volatile(
        "mma.sync.aligned.m16n8k8.row.col.f32.tf32.tf32.f32 "
        "{%0,%1,%2,%3}, {%4,%5,%6,%7}, {%8,%9}, {%0,%1,%2,%3};\n"
        : "+f"(c[0]), "+f"(c[1]), "+f"(c[2]), "+f"(c[3])
        : "r"(a0), "r"(a1), "r"(a2), "r"(a3), "r"(b0), "r"(b1));
}

__device__ __forceinline__ void mma_f16(float c[4],
    unsigned a0, unsigned a1, unsigned a2, unsigned a3,
    unsigned b0, unsigned b1)
{
    asm volatile(
        "mma.sync.aligned.m16n8k16.row.col.f32.f16.f16.f32 "
        "{%0,%1,%2,%3}, {%4,%5,%6,%7}, {%8,%9}, {%0,%1,%2,%3};\n"
        : "+f"(c[0]), "+f"(c[1]), "+f"(c[2]), "+f"(c[3])
        : "r"(a0), "r"(a1), "r"(a2), "r"(a3), "r"(b0), "r"(b1));
}

__device__ __forceinline__ void cp16(void* s, const void* g) {
    unsigned sa = (unsigned)__cvta_generic_to_shared(s);
    asm volatile("cp.async.cg.shared.global [%0], [%1], 16;\n" :: "r"(sa), "l"(g));
}
#define CP_COMMIT() asm volatile("cp.async.commit_group;\n")
#define CP_WAIT(N)  asm volatile("cp.async.wait_group %0;\n" :: "n"(N))

// scale folded into Q: 1/sqrt(64) * log2(e)
#define QSCALE 0.1803368801111204f

// ---------------------------------------------------------------------------
// Kernel 0: pre-round inputs to tf32 (cvt-free cp.async GEMM mainloops)
// ---------------------------------------------------------------------------
__global__ void prepass(const float* __restrict__ x,
                        const float* __restrict__ wq,
                        const float* __restrict__ wo)
{
    const int stride = gridDim.x * blockDim.x;
    const int tid = blockIdx.x * blockDim.x + threadIdx.x;
    const int nx = NTOK * E_DIM / 4, nq = E_DIM * QKV_N / 4, no = E_DIM * E_DIM / 4;
    for (int i = tid; i < nx; i += stride) {
        float4 v = ((const float4*)x)[i];
        ((float4*)g_Xr)[i] = make_float4(f2tf32f(v.x), f2tf32f(v.y), f2tf32f(v.z), f2tf32f(v.w));
    }
    for (int i = tid; i < nq; i += stride) {
        float4 v = ((const float4*)wq)[i];
        ((float4*)g_Wq)[i] = make_float4(f2tf32f(v.x), f2tf32f(v.y), f2tf32f(v.z), f2tf32f(v.w));
    }
    for (int i = tid; i < no; i += stride) {
        float4 v = ((const float4*)wo)[i];
        ((float4*)g_Wo)[i] = make_float4(f2tf32f(v.x), f2tf32f(v.y), f2tf32f(v.z), f2tf32f(v.w));
    }
}

// ---------------------------------------------------------------------------
// GEMM common (R12-validated): 128x128 tile, BK=32, 3-stage cp.async, tf32.
// ---------------------------------------------------------------------------
#define GA_ST 36
#define GB_ST 136
#define GA_SZ (128 * GA_ST)
#define GB_SZ (32 * GB_ST)
#define GEMM_SMEM (3 * (GA_SZ + GB_SZ) * 4)

// ---------------------------------------------------------------------------
// Kernel 1: QKV projection (tf32 MMA, R12-validated mainloop).
// Epilogue: Q/K fp16 [B,H,S,D] (Q pre-scaled), V fp16 transposed [B,H,D,S].
// ---------------------------------------------------------------------------
__global__ __launch_bounds__(256) void qkv_gemm(const float* __restrict__ bias)
{
    extern __shared__ unsigned smg[];
    unsigned* Asb = smg;                 // [3][128][GA_ST]
    unsigned* Bsb = smg + 3 * GA_SZ;     // [3][32][GB_ST]

    const int t    = threadIdx.x;
    const int lane = t & 31, warp = t >> 5;
    const int gid  = lane >> 2, tig = lane & 3;
    const int wm   = warp >> 2, wn = warp & 3;
    const int row0 = blockIdx.y * 128;
    const int col0 = blockIdx.x * 128;

    float acc[4][4][4] = {};

    auto stage = [&](int buf, int kk) {
        unsigned* A = Asb + buf * GA_SZ;
        unsigned* B = Bsb + buf * GB_SZ;
#pragma unroll
        for (int i = 0; i < 4; i++) {
            int c = t + i * 256;
            int rr = c >> 3, c4 = (c & 7) * 4;
            cp16(&A[rr * GA_ST + c4], &g_Xr[(size_t)(row0 + rr) * E_DIM + kk + c4]);
        }
#pragma unroll
        for (int i = 0; i < 4; i++) {
            int c = t + i * 256;
            int rr = c >> 5, c4 = (c & 31) * 4;
            cp16(&B[rr * GB_ST + c4], &g_Wq[(size_t)(kk + rr) * QKV_N + col0 + c4]);
        }
        CP_COMMIT();
    };

    const int NT = E_DIM / 32;   // 24
    stage(0, 0);
    stage(1, 32);
    int buf = 0;
    for (int it = 0; it < NT; it++) {
        if (it + 2 < NT)      { stage((it + 2) % 3, (it + 2) * 32); CP_WAIT(2); }
        else if (it + 1 < NT) { CP_WAIT(1); }
        else                  { CP_WAIT(0); }
        __syncthreads();
        unsigned* A = Asb + buf * GA_SZ;
        unsigned* B = Bsb + buf * GB_SZ;
#pragma unroll
        for (int kf = 0; kf < 4; kf++) {
            unsigned a[4][4], b[4][2];
#pragma unroll
            for (int mf = 0; mf < 4; mf++) {
                int m = wm * 64 + mf * 16 + gid;
                a[mf][0] = A[m * GA_ST + kf * 8 + tig];
                a[mf][1] = A[(m + 8) * GA_ST + kf * 8 + tig];
                a[mf][2] = A[m * GA_ST + kf * 8 + tig + 4];
                a[mf][3] = A[(m + 8) * GA_ST + kf * 8 + tig + 4];
            }
#pragma unroll
            for (int nf = 0; nf < 4; nf++) {
                int n = wn * 32 + nf * 8 + gid;
                b[nf][0] = B[(kf * 8 + tig) * GB_ST + n];
                b[nf][1] = B[(kf * 8 + tig + 4) * GB_ST + n];
            }
#pragma unroll
            for (int mf = 0; mf < 4; mf++)
#pragma unroll
                for (int nf = 0; nf < 4; nf++)
                    mma_tf32(acc[mf][nf], a[mf][0], a[mf][1], a[mf][2], a[mf][3],
                             b[nf][0], b[nf][1]);
        }
        __syncthreads();
        buf = (buf + 1) % 3;
    }

    // Epilogue: bias + scatter. Q/K: fp16 [B,H,S,D]. V: fp16 [B,H,D,S].
    const int part = col0 / E_DIM;

    if (part < 2) {
        __half* dst = (part == 0) ? g_Q : g_K;
        const float qs = (part == 0) ? QSCALE : 1.0f;
#pragma unroll
        for (int nf = 0; nf < 4; nf++) {
            int cg = col0 + wn * 32 + nf * 8 + 2 * tig;
            float b0v = bias[cg], b1v = bias[cg + 1];
            int c = cg % E_DIM;
            int h = c >> 6, d = c & 63;
#pragma unroll
            for (int mf = 0; mf < 4; mf++) {
#pragma unroll
                for (int rr = 0; rr < 2; rr++) {
                    int m = row0 + wm * 64 + mf * 16 + gid + rr * 8;
                    int bb = m >> 12, s = m & 4095;
                    size_t o = ((size_t)(bb * NH + h) * S_LEN + s) * HD + d;
                    *(__half2*)&dst[o] = __floats2half2_rn(
                        (acc[mf][nf][rr * 2]     + b0v) * qs,
                        (acc[mf][nf][rr * 2 + 1] + b1v) * qs);
                }
            }
        }
    } else {
#pragma unroll
        for (int nf = 0; nf < 4; nf++) {
            int cg = col0 + wn * 32 + nf * 8 + 2 * tig;
            float b0v = bias[cg], b1v = bias[cg + 1];
            int c = cg % E_DIM;
            int h = c >> 6, d = c & 63;
#pragma unroll
            for (int mf = 0; mf < 4; mf++) {
#pragma unroll
                for (int rr = 0; rr < 2; rr++) {
                    int m = row0 + wm * 64 + mf * 16 + gid + rr * 8;
                    int bb = m >> 12, s = m & 4095;
                    __half* vb =
                        g_Vt + ((size_t)(bb * NH + h) * HD + d) * S_LEN + s;
                    vb[0]     = __float2half_rn(acc[mf][nf][rr * 2]     + b0v);
                    vb[S_LEN] = __float2half_rn(acc[mf][nf][rr * 2 + 1] + b1v);
                }
            }
        }
    }
}

// ---------------------------------------------------------------------------
// Kernel 2: causal flash attention. fp16 QK^T + fp16 PV (k16), f16x2 exp,
// BN=128 KV tiles processed as two 64-col halves per stage/sync pair.
// Double-buffered cp.async K+Vt. Zero-copy P fragments.
// ---------------------------------------------------------------------------
#define QW   36                          // Q row stride, words
#define KW   36                          // K row stride, words (128 s-rows/tile)
#define VTW  68                          // Vt d-row stride, words (128 halves+pad)
#define KBUFW (128 * KW)
#define VBUFW (64 * VTW)
#define ATTN_SMEM ((128 * QW + 2 * KBUFW + 2 * VBUFW) * 4)   // 90112 B

__global__ __launch_bounds__(256, 2) void attn_kernel()
{
    extern __shared__ unsigned sm[];
    unsigned* Qs  = sm;                        // [128][QW]  fp16
    unsigned* Ksb = sm + 128 * QW;             // [2][128][KW] fp16
    unsigned* Vsb = Ksb + 2 * KBUFW;           // [2][64][VTW] fp16

    const int t    = threadIdx.x;
    const int lane = t & 31, warp = t >> 5;
    const int gid  = lane >> 2, tig = lane & 3;

    // descending-size schedule: biggest q-blocks first
    const int r  = blockIdx.x;
    const int qb = (NQB - 1) - r / (NH * BATCH);
    const int hb = r % (NH * BATCH);
    const int h  = hb % NH;
    const int b  = hb / NH;
    const int q0 = qb * 128;

    const size_t base = (size_t)(b * NH + h) * S_LEN * HD;
    const __half* Qp = g_Q + base;
    const __half* Kp = g_K + base;
    const __half* Vtp = g_Vt + (size_t)(b * NH + h) * HD * S_LEN;

    auto stage_kv = [&](int buf, int j0) {      // stages 128 KV columns
        unsigned* K = Ksb + buf * KBUFW;
        unsigned* V = Vsb + buf * VBUFW;
#pragma unroll
        for (int i = 0; i < 4; i++) {            // K: 128 rows x 128B
            int c = t + i * 256;
            int row = c >> 3, seg = c & 7;
            cp16(&K[row * KW + seg * 4], &Kp[(size_t)(j0 + row) * HD + seg * 8]);
        }
#pragma unroll
        for (int i = 0; i < 4; i++) {            // Vt: 64 d-rows x 256B
            int c = t + i * 256;
            int row = c >> 4, seg = c & 15;
            cp16(&V[row * VTW + seg * 4], &Vtp[(size_t)row * S_LEN + j0 + seg * 8]);
        }
        CP_COMMIT();
    };

    // ---- stage Q (128 rows x 128B fp16) ----
#pragma unroll
    for (int i = 0; i < 4; i++) {
        int c = t + i * 256;
        int row = c >> 3, seg = c & 7;
        cp16(&Qs[row * QW + seg * 4], &Qp[(size_t)(q0 + row) * HD + seg * 8]);
    }
    CP_COMMIT();
    stage_kv(0, 0);
    CP_WAIT(1);                           // Q ready; KV0 in flight
    __syncthreads();

    const int mrow = warp * 16 + gid;
    unsigned qa[4][4];
#pragma unroll
    for (int kf = 0; kf < 4; kf++) {
        qa[kf][0] = Qs[mrow * QW + kf * 8 + tig];
        qa[kf][1] = Qs[(mrow + 8) * QW + kf * 8 + tig];
        qa[kf][2] = Qs[mrow * QW + kf * 8 + tig + 4];
        qa[kf][3] = Qs[(mrow + 8) * QW + kf * 8 + tig + 4];
    }

    float ml0 = -1e30f, ml1 = -1e30f, l0 = 0.f, l1 = 0.f;
    float o[8][4] = {};

    const int row0g = q0 + warp * 16 + gid;
    const int row1g = row0g + 8;
    const int wrmin = q0 + warp * 16;
    const int wrmax = wrmin + 15;

    for (int jt = 0; jt <= qb; jt++) {           // 128-col tiles, exact cover
        const int j0 = jt << 7;
        const int buf = jt & 1;
        if (jt < qb) { stage_kv(buf ^ 1, j0 + 128); CP_WAIT(1); }
        else         { CP_WAIT(0); }
        __syncthreads();

        const unsigned* Ks = Ksb + buf * KBUFW;
        const unsigned* Vt32 = Vsb + buf * VBUFW;

#pragma unroll
        for (int h2 = 0; h2 < 2; h2++) {         // two 64-col halves
            const int jj = j0 + h2 * 64;
            if (jj <= wrmax) {
                const unsigned* Kh = Ks + (h2 * 64) * KW;
                const int vw = h2 * 32;          // V word offset for this half

                // ---- S = Q K^T (fp16 k16, log2-scaled) ----
                float s[8][4] = {};
#pragma unroll
                for (int kf = 0; kf < 4; kf++) {
#pragma unroll
                    for (int nf = 0; nf < 8; nf++) {
                        unsigned b0 = Kh[(nf * 8 + gid) * KW + kf * 8 + tig];
                        unsigned b1 = Kh[(nf * 8 + gid) * KW + kf * 8 + tig + 4];
                        mma_f16(s[nf], qa[kf][0], qa[kf][1], qa[kf][2], qa[kf][3], b0, b1);
                    }
                }

                // ---- causal mask (diagonal-adjacent halves only) ----
                if (jj + 63 > wrmin) {
#pragma unroll
                    for (int nf = 0; nf < 8; nf++) {
                        int c = jj + nf * 8 + 2 * tig;
                        if (c     > row0g) s[nf][0] = -1e30f;
                        if (c + 1 > row0g) s[nf][1] = -1e30f;
                        if (c     > row1g) s[nf][2] = -1e30f;
                        if (c + 1 > row1g) s[nf][3] = -1e30f;
                    }
                }

                // ---- row max (base-2 domain) ----
                float mx0 = ml0, mx1 = ml1;
#pragma unroll
                for (int nf = 0; nf < 8; nf++) {
                    mx0 = fmaxf(mx0, fmaxf(s[nf][0], s[nf][1]));
                    mx1 = fmaxf(mx1, fmaxf(s[nf][2], s[nf][3]));
                }
                mx0 = fmaxf(mx0, __shfl_xor_sync(0xffffffffu, mx0, 1));
                mx0 = fmaxf(mx0, __shfl_xor_sync(0xffffffffu, mx0, 2));
                mx1 = fmaxf(mx1, __shfl_xor_sync(0xffffffffu, mx1, 1));
                mx1 = fmaxf(mx1, __shfl_xor_sync(0xffffffffu, mx1, 2));

                const float sc0 = ex2f(ml0 - mx0), sc1 = ex2f(ml1 - mx1);
                ml0 = mx0; ml1 = mx1;
#pragma unroll
                for (int nf = 0; nf < 8; nf++) {
                    o[nf][0] *= sc0; o[nf][1] *= sc0;
                    o[nf][2] *= sc1; o[nf][3] *= sc1;
                }

                // ---- f16x2 exp directly into P fragments; sum rounded P ----
                unsigned pA[4][4];
                float sum0 = 0.f, sum1 = 0.f;
#pragma unroll
                for (int nf = 0; nf < 8; nf++) {
                    __half2 d01 = __floats2half2_rn(s[nf][0] - mx0, s[nf][1] - mx0);
                    __half2 d23 = __floats2half2_rn(s[nf][2] - mx1, s[nf][3] - mx1);
                    unsigned p01 = ex2_h2(*(unsigned*)&d01);
                    unsigned p23 = ex2_h2(*(unsigned*)&d23);
                    float2 f01 = __half22float2(*(__half2*)&p01);
                    float2 f23 = __half22float2(*(__half2*)&p23);
                    sum0 += f01.x + f01.y;
                    sum1 += f23.x + f23.y;
                    int g = nf >> 1;
                    if ((nf & 1) == 0) { pA[g][0] = p01; pA[g][1] = p23; }
                    else               { pA[g][2] = p01; pA[g][3] = p23; }
                }

                sum0 += __shfl_xor_sync(0xffffffffu, sum0, 1);
                sum0 += __shfl_xor_sync(0xffffffffu, sum0, 2);
                sum1 += __shfl_xor_sync(0xffffffffu, sum1, 1);
                sum1 += __shfl_xor_sync(0xffffffffu, sum1, 2);
                l0 = l0 * sc0 + sum0;
                l1 = l1 * sc1 + sum1;

                // ---- O += P V  (fp16 k16; B = Vt[d][s] direct) ----
#pragma unroll
                for (int g = 0; g < 4; g++) {
#pragma unroll
                    for (int nf = 0; nf < 8; nf++) {
                        unsigned vb0 = Vt32[(nf * 8 + gid) * VTW + vw + g * 8 + tig];
                        unsigned vb1 = Vt32[(nf * 8 + gid) * VTW + vw + g * 8 + tig + 4];
                        mma_f16(o[nf], pA[g][0], pA[g][1], pA[g][2], pA[g][3], vb0, vb1);
                    }
                }
            }
        }
        __syncthreads();
    }

    // ---- normalize + tf32-round + write attended (fp32) [B*S, E] ----
    const float inv0 = 1.0f / l0, inv1 = 1.0f / l1;
#pragma unroll
    for (int nf = 0; nf < 8; nf++) {
        int col = h * HD + nf * 8 + 2 * tig;
        float2 v0 = make_float2(f2tf32f(o[nf][0] * inv0), f2tf32f(o[nf][1] * inv0));
        float2 v1 = make_float2(f2tf32f(o[nf][2] * inv1), f2tf32f(o[nf][3] * inv1));
        *(float2*)&g_Att[(size_t)(b * S_LEN + row0g) * E_DIM + col] = v0;
        *(float2*)&g_Att[(size_t)(b * S_LEN + row1g) * E_DIM + col] = v1;
    }
}

// ---------------------------------------------------------------------------
// Kernel 3: output projection (tf32 MMA, R12-validated).
// ---------------------------------------------------------------------------
__global__ __launch_bounds__(256) void out_gemm(
    const float* __restrict__ bias, float* __restrict__ out)
{
    extern __shared__ unsigned smg[];
    unsigned* Asb = smg;
    unsigned* Bsb = smg + 3 * GA_SZ;

    const int t    = threadIdx.x;
    const int lane = t & 31, warp = t >> 5;
    const int gid  = lane >> 2, tig = lane & 3;
    const int wm   = warp >> 2, wn = warp & 3;
    const int row0 = blockIdx.y * 128;
    const int col0 = blockIdx.x * 128;

    float acc[4][4][4] = {};

    auto stage = [&](int buf, int kk) {
        unsigned* A = Asb + buf * GA_SZ;
        unsigned* B = Bsb + buf * GB_SZ;
#pragma unroll
        for (int i = 0; i < 4; i++) {
            int c = t + i * 256;
            int rr = c >> 3, c4 = (c & 7) * 4;
            cp16(&A[rr * GA_ST + c4], &g_Att[(size_t)(row0 + rr) * E_DIM + kk + c4]);
        }
#pragma unroll
        for (int i = 0; i < 4; i++) {
            int c = t + i * 256;
            int rr = c >> 5, c4 = (c & 31) * 4;
            cp16(&B[rr * GB_ST + c4], &g_Wo[(size_t)(kk + rr) * E_DIM + col0 + c4]);
        }
        CP_COMMIT();
    };

    const int NT = E_DIM / 32;
    stage(0, 0);
    stage(1, 32);
    int buf = 0;
    for (int it = 0; it < NT; it++) {
        if (it + 2 < NT)      { stage((it + 2) % 3, (it + 2) * 32); CP_WAIT(2); }
        else if (it + 1 < NT) { CP_WAIT(1); }
        else                  { CP_WAIT(0); }
        __syncthreads();
        unsigned* A = Asb + buf * GA_SZ;
        unsigned* B = Bsb + buf * GB_SZ;
#pragma unroll
        for (int kf = 0; kf < 4; kf++) {
            unsigned a[4][4], b[4][2];
#pragma unroll
            for (int mf = 0; mf < 4; mf++) {
                int m = wm * 64 + mf * 16 + gid;
                a[mf][0] = A[m * GA_ST + kf * 8 + tig];
                a[mf][1] = A[(m + 8) * GA_ST + kf * 8 + tig];
                a[mf][2] = A[m * GA_ST + kf * 8 + tig + 4];
                a[mf][3] = A[(m + 8) * GA_ST + kf * 8 + tig + 4];
            }
#pragma unroll
            for (int nf = 0; nf < 4; nf++) {
                int n = wn * 32 + nf * 8 + gid;
                b[nf][0] = B[(kf * 8 + tig) * GB_ST + n];
                b[nf][1] = B[(kf * 8 + tig + 4) * GB_ST + n];
            }
#pragma unroll
            for (int mf = 0; mf < 4; mf++)
#pragma unroll
                for (int nf = 0; nf < 4; nf++)
                    mma_tf32(acc[mf][nf], a[mf][0], a[mf][1], a[mf][2], a[mf][3],
                             b[nf][0], b[nf][1]);
        }
        __syncthreads();
        buf = (buf + 1) % 3;
    }

#pragma unroll
    for (int nf = 0; nf < 4; nf++) {
        int c = col0 + wn * 32 + nf * 8 + 2 * tig;
        float b0v = bias[c], b1v = bias[c + 1];
#pragma unroll
        for (int mf = 0; mf < 4; mf++) {
#pragma unroll
            for (int rr = 0; rr < 2; rr++) {
                int m = row0 + wm * 64 + mf * 16 + gid + rr * 8;
                float2 vv;
                vv.x = acc[mf][nf][rr * 2]     + b0v;
                vv.y = acc[mf][nf][rr * 2 + 1] + b1v;
                *(float2*)&out[(size_t)m * E_DIM + c] = vv;
            }
        }
    }
}

// ---------------------------------------------------------------------------
extern "C" void kernel_launch(void* const* d_in, const int* in_sizes, int n_in,
                              void* d_out, int out_size)
{
    const float* x     = (const float*)d_in[0];
    const float* w_qkv = (const float*)d_in[1];
    const float* b_qkv = (const float*)d_in[2];
    const float* w_out = (const float*)d_in[3];
    const float* b_out = (const float*)d_in[4];
    float* out = (float*)d_out;

    cudaFuncSetAttribute(attn_kernel,
                         cudaFuncAttributeMaxDynamicSharedMemorySize, ATTN_SMEM);
    cudaFuncSetAttribute(qkv_gemm,
                         cudaFuncAttributeMaxDynamicSharedMemorySize, GEMM_SMEM);
    cudaFuncSetAttribute(out_gemm,
                         cudaFuncAttributeMaxDynamicSharedMemorySize, GEMM_SMEM);

    prepass<<<1024, 256>>>(x, w_qkv, w_out);

    dim3 g1(QKV_N / 128, NTOK / 128);     // (18, 64)
    qkv_gemm<<<g1, 256, GEMM_SMEM>>>(b_qkv);

    attn_kernel<<<NQB * NH * BATCH, 256, ATTN_SMEM>>>();   // 768, descending

    dim3 g3(E_DIM / 128, NTOK / 128);     // (6, 64)
    out_gemm<<<g3, 256, GEMM_SMEM>>>(b_out, out);
}

// round 17
// speedup vs baseline: 1.7558x; 1.1139x over previous
#include <cuda_runtime.h>
#include <cuda_fp16.h>

#define S_LEN  4096
#define BATCH  2
#define NH     12
#define HD     64
#define E_DIM  768
#define QKV_N  2304
#define NTOK   (BATCH * S_LEN)
#define NQB    (S_LEN / 128)          // 32 q-blocks per (b,h)

// Scratch (allocation-free rule: __device__ globals).
__device__ __half g_Xh[(size_t)NTOK * E_DIM];            // fp16 x
__device__ __half g_Wqt[(size_t)QKV_N * E_DIM];          // fp16 w_qkv^T [n][k]
__device__ float  g_Wo[(size_t)E_DIM * E_DIM];           // tf32-rounded w_out
__device__ __half g_Q[(size_t)BATCH * NH * S_LEN * HD];  // fp16, pre-scaled 0.125*log2e
__device__ __half g_K[(size_t)BATCH * NH * S_LEN * HD];  // fp16
__device__ __half g_Vt[(size_t)BATCH * NH * HD * S_LEN]; // fp16, [b][h][d][s]
__device__ float  g_Att[(size_t)NTOK * E_DIM];           // attended, tf32-rounded

// ---------------------------------------------------------------------------
// helpers
// ---------------------------------------------------------------------------
__device__ __forceinline__ unsigned f2tf32(float f) {
    unsigned u;
    asm("cvt.rna.tf32.f32 %0, %1;" : "=r"(u) : "f"(f));
    return u;
}
__device__ __forceinline__ float f2tf32f(float f) {
    return __uint_as_float(f2tf32(f));
}
__device__ __forceinline__ float ex2f(float x) {
    float y;
    asm("ex2.approx.f32 %0, %1;" : "=f"(y) : "f"(x));
    return y;
}
__device__ __forceinline__ unsigned ex2_h2(unsigned x) {   // f16x2 2^x
    unsigned y;
    asm("ex2.approx.f16x2 %0, %1;" : "=r"(y) : "r"(x));
    return y;
}

__device__ __forceinline__ void mma_tf32(float c[4],
    unsigned a0, unsigned a1, unsigned a2, unsigned a3,
    unsigned b0, unsigned b1)
{
    asm volatile(
        "mma.sync.aligned.m16n8k8.row.col.f32.tf32.tf32.f32 "
        "{%0,%1,%2,%3}, {%4,%5,%6,%7}, {%8,%9}, {%0,%1,%2,%3};\n"
        : "+f"(c[0]), "+f"(c[1]), "+f"(c[2]), "+f"(c[3])
        : "r"(a0), "r"(a1), "r"(a2), "r"(a3), "r"(b0), "r"(b1));
}

__device__ __forceinline__ void mma_f16(float c[4],
    unsigned a0, unsigned a1, unsigned a2, unsigned a3,
    unsigned b0, unsigned b1)
{
    asm volatile(
        "mma.sync.aligned.m16n8k16.row.col.f32.f16.f16.f32 "
        "{%0,%1,%2,%3}, {%4,%5,%6,%7}, {%8,%9}, {%0,%1,%2,%3};\n"
        : "+f"(c[0]), "+f"(c[1]), "+f"(c[2]), "+f"(c[3])
        : "r"(a0), "r"(a1), "r"(a2), "r"(a3), "r"(b0), "r"(b1));
}

__device__ __forceinline__ void cp16(void* s, const void* g) {
    unsigned sa = (unsigned)__cvta_generic_to_shared(s);
    asm volatile("cp.async.cg.shared.global [%0], [%1], 16;\n" :: "r"(sa), "l"(g));
}
#define CP_COMMIT() asm volatile("cp.async.commit_group;\n")
#define CP_WAIT(N)  asm volatile("cp.async.wait_group %0;\n" :: "n"(N))

// scale folded into Q: 1/sqrt(64) * log2(e)
#define QSCALE 0.1803368801111204f

// ---------------------------------------------------------------------------
// Kernel 0: prepass (validated launch shape). Writes:
//   g_Xh  : fp16 x (elementwise)
//   g_Wqt : fp16 w_qkv TRANSPOSED [n][k] (coalesced read, strided write —
//           no tiles, no smem; trivially auditable)
//   g_Wo  : tf32-rounded w_out (unchanged, for tf32 out_gemm)
// ---------------------------------------------------------------------------
__global__ void prepass(const float* __restrict__ x,
                        const float* __restrict__ wq,
                        const float* __restrict__ wo)
{
    const int stride = gridDim.x * blockDim.x;
    const int tid = blockIdx.x * blockDim.x + threadIdx.x;
    const int nx = NTOK * E_DIM / 4;
    const int nw = E_DIM * QKV_N;
    const int no = E_DIM * E_DIM / 4;
    for (int i = tid; i < nx; i += stride) {
        float4 v = ((const float4*)x)[i];
        __half2* d = (__half2*)g_Xh + 2 * i;
        d[0] = __floats2half2_rn(v.x, v.y);
        d[1] = __floats2half2_rn(v.z, v.w);
    }
    for (int i = tid; i < nw; i += stride) {
        int k = i / QKV_N;              // src row   (coalesced read over n)
        int n = i - k * QKV_N;          // src col
        g_Wqt[(size_t)n * E_DIM + k] = __float2half_rn(wq[i]);
    }
    for (int i = tid; i < no; i += stride) {
        float4 v = ((const float4*)wo)[i];
        ((float4*)g_Wo)[i] = make_float4(f2tf32f(v.x), f2tf32f(v.y), f2tf32f(v.z), f2tf32f(v.w));
    }
}

// ---------------------------------------------------------------------------
// tf32 GEMM defines (out_gemm, R12-validated)
// ---------------------------------------------------------------------------
#define GA_ST 36
#define GB_ST 136
#define GA_SZ (128 * GA_ST)
#define GB_SZ (32 * GB_ST)
#define GEMM_SMEM (3 * (GA_SZ + GB_SZ) * 4)

// fp16 qkv GEMM: 128x128 tile, BK=32, 3-stage cp.async, m16n8k16.
#define HST   20                         // row stride in 32-bit words (16+4 pad)
#define HBUF  (128 * HST)
#define QKV_SMEM (3 * 2 * HBUF * 4)      // 61440 B

// ---------------------------------------------------------------------------
// Kernel 1: QKV projection, fp16 MMA. A = g_Xh [m][k], B = g_Wqt [n][k].
// Fragment patterns identical to the R15/R16-validated attention paths.
// Epilogue byte-identical to R16 (Q/K fp16 [B,H,S,D], V fp16 [B,H,D,S]).
// ---------------------------------------------------------------------------
__global__ __launch_bounds__(256) void qkv_gemm(const float* __restrict__ bias)
{
    extern __shared__ unsigned smg[];
    unsigned* Asb = smg;                 // [3][128][HST]
    unsigned* Bsb = smg + 3 * HBUF;      // [3][128][HST]

    const int t    = threadIdx.x;
    const int lane = t & 31, warp = t >> 5;
    const int gid  = lane >> 2, tig = lane & 3;
    const int wm   = warp >> 2, wn = warp & 3;
    const int row0 = blockIdx.y * 128;
    const int col0 = blockIdx.x * 128;

    float acc[4][4][4] = {};

    auto stage = [&](int buf, int kk) {
        unsigned* A = Asb + buf * HBUF;
        unsigned* B = Bsb + buf * HBUF;
#pragma unroll
        for (int i = 0; i < 2; i++) {
            int c = t + i * 256;
            int rr = c >> 2, seg = c & 3;
            cp16(&A[rr * HST + seg * 4], &g_Xh[(size_t)(row0 + rr) * E_DIM + kk + seg * 8]);
        }
#pragma unroll
        for (int i = 0; i < 2; i++) {
            int c = t + i * 256;
            int rr = c >> 2, seg = c & 3;
            cp16(&B[rr * HST + seg * 4], &g_Wqt[(size_t)(col0 + rr) * E_DIM + kk + seg * 8]);
        }
        CP_COMMIT();
    };

    const int NT = E_DIM / 32;   // 24
    stage(0, 0);
    stage(1, 32);
    int buf = 0;
    for (int it = 0; it < NT; it++) {
        if (it + 2 < NT)      { stage((it + 2) % 3, (it + 2) * 32); CP_WAIT(2); }
        else if (it + 1 < NT) { CP_WAIT(1); }
        else                  { CP_WAIT(0); }
        __syncthreads();
        unsigned* A = Asb + buf * HBUF;
        unsigned* B = Bsb + buf * HBUF;
#pragma unroll
        for (int kf = 0; kf < 2; kf++) {
            unsigned a[4][4], b[4][2];
#pragma unroll
            for (int mf = 0; mf < 4; mf++) {
                int m = wm * 64 + mf * 16 + gid;
                a[mf][0] = A[m * HST + kf * 8 + tig];
                a[mf][1] = A[(m + 8) * HST + kf * 8 + tig];
                a[mf][2] = A[m * HST + kf * 8 + tig + 4];
                a[mf][3] = A[(m + 8) * HST + kf * 8 + tig + 4];
            }
#pragma unroll
            for (int nf = 0; nf < 4; nf++) {
                int n = wn * 32 + nf * 8 + gid;
                b[nf][0] = B[n * HST + kf * 8 + tig];
                b[nf][1] = B[n * HST + kf * 8 + tig + 4];
            }
#pragma unroll
            for (int mf = 0; mf < 4; mf++)
#pragma unroll
                for (int nf = 0; nf < 4; nf++)
                    mma_f16(acc[mf][nf], a[mf][0], a[mf][1], a[mf][2], a[mf][3],
                            b[nf][0], b[nf][1]);
        }
        __syncthreads();
        buf = (buf + 1) % 3;
    }

    // Epilogue (byte-identical to R16): bias + scatter.
    const int part = col0 / E_DIM;

    if (part < 2) {
        __half* dst = (part == 0) ? g_Q : g_K;
        const float qs = (part == 0) ? QSCALE : 1.0f;
#pragma unroll
        for (int nf = 0; nf < 4; nf++) {
            int cg = col0 + wn * 32 + nf * 8 + 2 * tig;
            float b0v = bias[cg], b1v = bias[cg + 1];
            int c = cg % E_DIM;
            int h = c >> 6, d = c & 63;
#pragma unroll
            for (int mf = 0; mf < 4; mf++) {
#pragma unroll
                for (int rr = 0; rr < 2; rr++) {
                    int m = row0 + wm * 64 + mf * 16 + gid + rr * 8;
                    int bb = m >> 12, s = m & 4095;
                    size_t o = ((size_t)(bb * NH + h) * S_LEN + s) * HD + d;
                    *(__half2*)&dst[o] = __floats2half2_rn(
                        (acc[mf][nf][rr * 2]     + b0v) * qs,
                        (acc[mf][nf][rr * 2 + 1] + b1v) * qs);
                }
            }
        }
    } else {
#pragma unroll
        for (int nf = 0; nf < 4; nf++) {
            int cg = col0 + wn * 32 + nf * 8 + 2 * tig;
            float b0v = bias[cg], b1v = bias[cg + 1];
            int c = cg % E_DIM;
            int h = c >> 6, d = c & 63;
#pragma unroll
            for (int mf = 0; mf < 4; mf++) {
#pragma unroll
                for (int rr = 0; rr < 2; rr++) {
                    int m = row0 + wm * 64 + mf * 16 + gid + rr * 8;
                    int bb = m >> 12, s = m & 4095;
                    __half* vb =
                        g_Vt + ((size_t)(bb * NH + h) * HD + d) * S_LEN + s;
                    vb[0]     = __float2half_rn(acc[mf][nf][rr * 2]     + b0v);
                    vb[S_LEN] = __float2half_rn(acc[mf][nf][rr * 2 + 1] + b1v);
                }
            }
        }
    }
}

// ---------------------------------------------------------------------------
// Kernel 2: causal flash attention — byte-identical to R16 (validated).
// ---------------------------------------------------------------------------
#define QW   36
#define KW   36
#define VTW  68
#define KBUFW (128 * KW)
#define VBUFW (64 * VTW)
#define ATTN_SMEM ((128 * QW + 2 * KBUFW + 2 * VBUFW) * 4)   // 90112 B

__global__ __launch_bounds__(256, 2) void attn_kernel()
{
    extern __shared__ unsigned sm[];
    unsigned* Qs  = sm;                        // [128][QW]  fp16
    unsigned* Ksb = sm + 128 * QW;             // [2][128][KW] fp16
    unsigned* Vsb = Ksb + 2 * KBUFW;           // [2][64][VTW] fp16

    const int t    = threadIdx.x;
    const int lane = t & 31, warp = t >> 5;
    const int gid  = lane >> 2, tig = lane & 3;

    const int r  = blockIdx.x;
    const int qb = (NQB - 1) - r / (NH * BATCH);
    const int hb = r % (NH * BATCH);
    const int h  = hb % NH;
    const int b  = hb / NH;
    const int q0 = qb * 128;

    const size_t base = (size_t)(b * NH + h) * S_LEN * HD;
    const __half* Qp = g_Q + base;
    const __half* Kp = g_K + base;
    const __half* Vtp = g_Vt + (size_t)(b * NH + h) * HD * S_LEN;

    auto stage_kv = [&](int buf, int j0) {
        unsigned* K = Ksb + buf * KBUFW;
        unsigned* V = Vsb + buf * VBUFW;
#pragma unroll
        for (int i = 0; i < 4; i++) {
            int c = t + i * 256;
            int row = c >> 3, seg = c & 7;
            cp16(&K[row * KW + seg * 4], &Kp[(size_t)(j0 + row) * HD + seg * 8]);
        }
#pragma unroll
        for (int i = 0; i < 4; i++) {
            int c = t + i * 256;
            int row = c >> 4, seg = c & 15;
            cp16(&V[row * VTW + seg * 4], &Vtp[(size_t)row * S_LEN + j0 + seg * 8]);
        }
        CP_COMMIT();
    };

#pragma unroll
    for (int i = 0; i < 4; i++) {
        int c = t + i * 256;
        int row = c >> 3, seg = c & 7;
        cp16(&Qs[row * QW + seg * 4], &Qp[(size_t)(q0 + row) * HD + seg * 8]);
    }
    CP_COMMIT();
    stage_kv(0, 0);
    CP_WAIT(1);
    __syncthreads();

    const int mrow = warp * 16 + gid;
    unsigned qa[4][4];
#pragma unroll
    for (int kf = 0; kf < 4; kf++) {
        qa[kf][0] = Qs[mrow * QW + kf * 8 + tig];
        qa[kf][1] = Qs[(mrow + 8) * QW + kf * 8 + tig];
        qa[kf][2] = Qs[mrow * QW + kf * 8 + tig + 4];
        qa[kf][3] = Qs[(mrow + 8) * QW + kf * 8 + tig + 4];
    }

    float ml0 = -1e30f, ml1 = -1e30f, l0 = 0.f, l1 = 0.f;
    float o[8][4] = {};

    const int row0g = q0 + warp * 16 + gid;
    const int row1g = row0g + 8;
    const int wrmin = q0 + warp * 16;
    const int wrmax = wrmin + 15;

    for (int jt = 0; jt <= qb; jt++) {
        const int j0 = jt << 7;
        const int buf = jt & 1;
        if (jt < qb) { stage_kv(buf ^ 1, j0 + 128); CP_WAIT(1); }
        else         { CP_WAIT(0); }
        __syncthreads();

        const unsigned* Ks = Ksb + buf * KBUFW;
        const unsigned* Vt32 = Vsb + buf * VBUFW;

#pragma unroll
        for (int h2 = 0; h2 < 2; h2++) {
            const int jj = j0 + h2 * 64;
            if (jj <= wrmax) {
                const unsigned* Kh = Ks + (h2 * 64) * KW;
                const int vw = h2 * 32;

                float s[8][4] = {};
#pragma unroll
                for (int kf = 0; kf < 4; kf++) {
#pragma unroll
                    for (int nf = 0; nf < 8; nf++) {
                        unsigned b0 = Kh[(nf * 8 + gid) * KW + kf * 8 + tig];
                        unsigned b1 = Kh[(nf * 8 + gid) * KW + kf * 8 + tig + 4];
                        mma_f16(s[nf], qa[kf][0], qa[kf][1], qa[kf][2], qa[kf][3], b0, b1);
                    }
                }

                if (jj + 63 > wrmin) {
#pragma unroll
                    for (int nf = 0; nf < 8; nf++) {
                        int c = jj + nf * 8 + 2 * tig;
                        if (c     > row0g) s[nf][0] = -1e30f;
                        if (c + 1 > row0g) s[nf][1] = -1e30f;
                        if (c     > row1g) s[nf][2] = -1e30f;
                        if (c + 1 > row1g) s[nf][3] = -1e30f;
                    }
                }

                float mx0 = ml0, mx1 = ml1;
#pragma unroll
                for (int nf = 0; nf < 8; nf++) {
                    mx0 = fmaxf(mx0, fmaxf(s[nf][0], s[nf][1]));
                    mx1 = fmaxf(mx1, fmaxf(s[nf][2], s[nf][3]));
                }
                mx0 = fmaxf(mx0, __shfl_xor_sync(0xffffffffu, mx0, 1));
                mx0 = fmaxf(mx0, __shfl_xor_sync(0xffffffffu, mx0, 2));
                mx1 = fmaxf(mx1, __shfl_xor_sync(0xffffffffu, mx1, 1));
                mx1 = fmaxf(mx1, __shfl_xor_sync(0xffffffffu, mx1, 2));

                const float sc0 = ex2f(ml0 - mx0), sc1 = ex2f(ml1 - mx1);
                ml0 = mx0; ml1 = mx1;
#pragma unroll
                for (int nf = 0; nf < 8; nf++) {
                    o[nf][0] *= sc0; o[nf][1] *= sc0;
                    o[nf][2] *= sc1; o[nf][3] *= sc1;
                }

                unsigned pA[4][4];
                float sum0 = 0.f, sum1 = 0.f;
#pragma unroll
                for (int nf = 0; nf < 8; nf++) {
                    __half2 d01 = __floats2half2_rn(s[nf][0] - mx0, s[nf][1] - mx0);
                    __half2 d23 = __floats2half2_rn(s[nf][2] - mx1, s[nf][3] - mx1);
                    unsigned p01 = ex2_h2(*(unsigned*)&d01);
                    unsigned p23 = ex2_h2(*(unsigned*)&d23);
                    float2 f01 = __half22float2(*(__half2*)&p01);
                    float2 f23 = __half22float2(*(__half2*)&p23);
                    sum0 += f01.x + f01.y;
                    sum1 += f23.x + f23.y;
                    int g = nf >> 1;
                    if ((nf & 1) == 0) { pA[g][0] = p01; pA[g][1] = p23; }
                    else               { pA[g][2] = p01; pA[g][3] = p23; }
                }

                sum0 += __shfl_xor_sync(0xffffffffu, sum0, 1);
                sum0 += __shfl_xor_sync(0xffffffffu, sum0, 2);
                sum1 += __shfl_xor_sync(0xffffffffu, sum1, 1);
                sum1 += __shfl_xor_sync(0xffffffffu, sum1, 2);
                l0 = l0 * sc0 + sum0;
                l1 = l1 * sc1 + sum1;

#pragma unroll
                for (int g = 0; g < 4; g++) {
#pragma unroll
                    for (int nf = 0; nf < 8; nf++) {
                        unsigned vb0 = Vt32[(nf * 8 + gid) * VTW + vw + g * 8 + tig];
                        unsigned vb1 = Vt32[(nf * 8 + gid) * VTW + vw + g * 8 + tig + 4];
                        mma_f16(o[nf], pA[g][0], pA[g][1], pA[g][2], pA[g][3], vb0, vb1);
                    }
                }
            }
        }
        __syncthreads();
    }

    const float inv0 = 1.0f / l0, inv1 = 1.0f / l1;
#pragma unroll
    for (int nf = 0; nf < 8; nf++) {
        int col = h * HD + nf * 8 + 2 * tig;
        float2 v0 = make_float2(f2tf32f(o[nf][0] * inv0), f2tf32f(o[nf][1] * inv0));
        float2 v1 = make_float2(f2tf32f(o[nf][2] * inv1), f2tf32f(o[nf][3] * inv1));
        *(float2*)&g_Att[(size_t)(b * S_LEN + row0g) * E_DIM + col] = v0;
        *(float2*)&g_Att[(size_t)(b * S_LEN + row1g) * E_DIM + col] = v1;
    }
}

// ---------------------------------------------------------------------------
// Kernel 3: output projection (tf32 MMA, R12-validated, unchanged).
// ---------------------------------------------------------------------------
__global__ __launch_bounds__(256) void out_gemm(
    const float* __restrict__ bias, float* __restrict__ out)
{
    extern __shared__ unsigned smg[];
    unsigned* Asb = smg;
    unsigned* Bsb = smg + 3 * GA_SZ;

    const int t    = threadIdx.x;
    const int lane = t & 31, warp = t >> 5;
    const int gid  = lane >> 2, tig = lane & 3;
    const int wm   = warp >> 2, wn = warp & 3;
    const int row0 = blockIdx.y * 128;
    const int col0 = blockIdx.x * 128;

    float acc[4][4][4] = {};

    auto stage = [&](int buf, int kk) {
        unsigned* A = Asb + buf * GA_SZ;
        unsigned* B = Bsb + buf * GB_SZ;
#pragma unroll
        for (int i = 0; i < 4; i++) {
            int c = t + i * 256;
            int rr = c >> 3, c4 = (c & 7) * 4;
            cp16(&A[rr * GA_ST + c4], &g_Att[(size_t)(row0 + rr) * E_DIM + kk + c4]);
        }
#pragma unroll
        for (int i = 0; i < 4; i++) {
            int c = t + i * 256;
            int rr = c >> 5, c4 = (c & 31) * 4;
            cp16(&B[rr * GB_ST + c4], &g_Wo[(size_t)(kk + rr) * E_DIM + col0 + c4]);
        }
        CP_COMMIT();
    };

    const int NT = E_DIM / 32;
    stage(0, 0);
    stage(1, 32);
    int buf = 0;
    for (int it = 0; it < NT; it++) {
        if (it + 2 < NT)      { stage((it + 2) % 3, (it + 2) * 32); CP_WAIT(2); }
        else if (it + 1 < NT) { CP_WAIT(1); }
        else                  { CP_WAIT(0); }
        __syncthreads();
        unsigned* A = Asb + buf * GA_SZ;
        unsigned* B = Bsb + buf * GB_SZ;
#pragma unroll
        for (int kf = 0; kf < 4; kf++) {
            unsigned a[4][4], b[4][2];
#pragma unroll
            for (int mf = 0; mf < 4; mf++) {
                int m = wm * 64 + mf * 16 + gid;
                a[mf][0] = A[m * GA_ST + kf * 8 + tig];
                a[mf][1] = A[(m + 8) * GA_ST + kf * 8 + tig];
                a[mf][2] = A[m * GA_ST + kf * 8 + tig + 4];
                a[mf][3] = A[(m + 8) * GA_ST + kf * 8 + tig + 4];
            }
#pragma unroll
            for (int nf = 0; nf < 4; nf++) {
                int n = wn * 32 + nf * 8 + gid;
                b[nf][0] = B[(kf * 8 + tig) * GB_ST + n];
                b[nf][1] = B[(kf * 8 + tig + 4) * GB_ST + n];
            }
#pragma unroll
            for (int mf = 0; mf < 4; mf++)
#pragma unroll
                for (int nf = 0; nf < 4; nf++)
                    mma_tf32(acc[mf][nf], a[mf][0], a[mf][1], a[mf][2], a[mf][3],
                             b[nf][0], b[nf][1]);
        }
        __syncthreads();
        buf = (buf + 1) % 3;
    }

#pragma unroll
    for (int nf = 0; nf < 4; nf++) {
        int c = col0 + wn * 32 + nf * 8 + 2 * tig;
        float b0v = bias[c], b1v = bias[c + 1];
#pragma unroll
        for (int mf = 0; mf < 4; mf++) {
#pragma unroll
            for (int rr = 0; rr < 2; rr++) {
                int m = row0 + wm * 64 + mf * 16 + gid + rr * 8;
                float2 vv;
                vv.x = acc[mf][nf][rr * 2]     + b0v;
                vv.y = acc[mf][nf][rr * 2 + 1] + b1v;
                *(float2*)&out[(size_t)m * E_DIM + c] = vv;
            }
        }
    }
}

// ---------------------------------------------------------------------------
extern "C" void kernel_launch(void* const* d_in, const int* in_sizes, int n_in,
                              void* d_out, int out_size)
{
    const float* x     = (const float*)d_in[0];
    const float* w_qkv = (const float*)d_in[1];
    const float* b_qkv = (const float*)d_in[2];
    const float* w_out = (const float*)d_in[3];
    const float* b_out = (const float*)d_in[4];
    float* out = (float*)d_out;

    cudaFuncSetAttribute(attn_kernel,
                         cudaFuncAttributeMaxDynamicSharedMemorySize, ATTN_SMEM);
    cudaFuncSetAttribute(qkv_gemm,
                         cudaFuncAttributeMaxDynamicSharedMemorySize, QKV_SMEM);
    cudaFuncSetAttribute(out_gemm,
                         cudaFuncAttributeMaxDynamicSharedMemorySize, GEMM_SMEM);

    prepass<<<1024, 256>>>(x, w_qkv, w_out);

    dim3 g1(QKV_N / 128, NTOK / 128);     // (18, 64)
    qkv_gemm<<<g1, 256, QKV_SMEM>>>(b_qkv);

    attn_kernel<<<NQB * NH * BATCH, 256, ATTN_SMEM>>>();   // 768, descending

    dim3 g3(E_DIM / 128, NTOK / 128);     // (6, 64)
    out_gemm<<<g3, 256, GEMM_SMEM>>>(b_out, out);
}